// round 3
// baseline (speedup 1.0000x reference)
#include <cuda_runtime.h>
#include <math.h>

#define NN    50000
#define EE    800000
#define INC   128
#define HIDC  64
#define NH    4
#define OUTC  64
#define F1    (NH * HIDC)        // 256
#define ET    (EE + NN)          // edges + self loops = 850000

// ---------------- scratch (device globals; no allocation) ----------------
__device__ float g_h1  [(size_t)NN * F1];    // x @ W1              51.2 MB
__device__ float g_out1[(size_t)NN * F1];    // conv1 aggregation / z in-place
__device__ float g_as1 [NN * NH];
__device__ float g_ad1 [NN * NH];
__device__ float g_den1[NN * NH];
__device__ float g_e1  [(size_t)ET * NH];    // exp(alpha) per edge 13.6 MB
__device__ float g_h2  [(size_t)NN * OUTC];  // z @ W2
__device__ float g_out2[(size_t)NN * OUTC];  // conv2 aggregation / z2 in-place
__device__ float g_as2 [NN];
__device__ float g_ad2 [NN];
__device__ float g_den2[NN];
__device__ float g_e2  [ET];

// ---------------- helpers ----------------
__device__ __forceinline__ void red_add_v4(float* a, float x, float y, float z, float w) {
    asm volatile("red.global.add.v4.f32 [%0], {%1,%2,%3,%4};"
                 :: "l"(a), "f"(x), "f"(y), "f"(z), "f"(w) : "memory");
}
__device__ __forceinline__ void red_add_v2(float* a, float x, float y) {
    asm volatile("red.global.add.v2.f32 [%0], {%1,%2};"
                 :: "l"(a), "f"(x), "f"(y) : "memory");
}
__device__ __forceinline__ float lrelu(float v) { return v > 0.f ? v : 0.2f * v; }

// ---------------- zero scratch accumulators ----------------
__global__ void zero_k() {
    size_t i = (size_t)blockIdx.x * blockDim.x + threadIdx.x;
    size_t stride = (size_t)gridDim.x * blockDim.x;
    for (size_t j = i; j < (size_t)NN * F1; j += stride) g_out1[j] = 0.f;
    for (size_t j = i; j < (size_t)NN * NH; j += stride) g_den1[j] = 0.f;
    for (size_t j = i; j < (size_t)NN * OUTC; j += stride) g_out2[j] = 0.f;
    for (size_t j = i; j < (size_t)NN; j += stride) g_den2[j] = 0.f;
}

// ---------------- SGEMM: C[M,N] = A[M,K] @ B[K,N] ----------------
// MODE 0: A = ext (x),     C = g_h1
// MODE 1: A = g_out1 (z),  C = g_h2
template <int MODE>
__global__ __launch_bounds__(256) void sgemm_k(const float* __restrict__ Aext,
                                               const float* __restrict__ B,
                                               int M, int N, int K) {
    const float* __restrict__ A = (MODE == 0) ? Aext : g_out1;
    float* __restrict__ C = (MODE == 0) ? g_h1 : g_h2;

    __shared__ __align__(16) float As[16][64];
    __shared__ __align__(16) float Bs[16][64];
    int tid = threadIdx.x;                 // 256 threads
    int tr = tid >> 4, tc = tid & 15;      // 16x16 thread grid, 4x4 micro-tile
    int rowBase = blockIdx.y * 64, colBase = blockIdx.x * 64;
    float acc[4][4] = {};

    for (int k0 = 0; k0 < K; k0 += 16) {
#pragma unroll
        for (int i = 0; i < 4; i++) {
            int idx = tid + i * 256;       // 0..1023 -> 64x16 A tile
            int m = idx >> 4, kk = idx & 15;
            int gm = rowBase + m;
            As[kk][m] = (gm < M) ? A[(size_t)gm * K + k0 + kk] : 0.f;
        }
#pragma unroll
        for (int i = 0; i < 4; i++) {
            int idx = tid + i * 256;       // 16x64 B tile (N % 64 == 0)
            int kk = idx >> 6, n = idx & 63;
            Bs[kk][n] = B[(size_t)(k0 + kk) * N + colBase + n];
        }
        __syncthreads();
#pragma unroll
        for (int kk = 0; kk < 16; kk++) {
            float4 a4 = *(const float4*)&As[kk][tr * 4];
            float4 b4 = *(const float4*)&Bs[kk][tc * 4];
            float av[4] = {a4.x, a4.y, a4.z, a4.w};
            float bv[4] = {b4.x, b4.y, b4.z, b4.w};
#pragma unroll
            for (int i = 0; i < 4; i++)
#pragma unroll
                for (int j = 0; j < 4; j++) acc[i][j] += av[i] * bv[j];
        }
        __syncthreads();
    }
#pragma unroll
    for (int i = 0; i < 4; i++) {
        int gm = rowBase + tr * 4 + i;
        if (gm < M) {
            float4 v = make_float4(acc[i][0], acc[i][1], acc[i][2], acc[i][3]);
            *(float4*)&C[(size_t)gm * N + colBase + tc * 4] = v;
        }
    }
}

// ---------------- attention dot products ----------------
// conv1: a_s[n,h] = <h1[n,h,:], att_src1[h,:]>  (att flat index == column index)
__global__ void attn1_k(const float* __restrict__ att_s, const float* __restrict__ att_d) {
    int g = blockIdx.x * blockDim.x + threadIdx.x;
    int w = g >> 5, lane = g & 31;
    if (w >= NN) return;
    const float* hp = g_h1 + (size_t)w * F1;
#pragma unroll
    for (int hh = 0; hh < NH; hh++) {
        float s = 0.f, d = 0.f;
#pragma unroll
        for (int i = 0; i < 2; i++) {
            int cc = hh * 64 + lane + i * 32;
            float v = hp[cc];
            s += v * att_s[cc];
            d += v * att_d[cc];
        }
#pragma unroll
        for (int o = 16; o; o >>= 1) {
            s += __shfl_down_sync(0xffffffffu, s, o);
            d += __shfl_down_sync(0xffffffffu, d, o);
        }
        if (!lane) { g_as1[w * NH + hh] = s; g_ad1[w * NH + hh] = d; }
    }
}

__global__ void attn2_k(const float* __restrict__ att_s, const float* __restrict__ att_d) {
    int g = blockIdx.x * blockDim.x + threadIdx.x;
    int w = g >> 5, lane = g & 31;
    if (w >= NN) return;
    const float* hp = g_h2 + (size_t)w * OUTC;
    float s = 0.f, d = 0.f;
#pragma unroll
    for (int i = 0; i < 2; i++) {
        int cc = lane + i * 32;
        float v = hp[cc];
        s += v * att_s[cc];
        d += v * att_d[cc];
    }
#pragma unroll
    for (int o = 16; o; o >>= 1) {
        s += __shfl_down_sync(0xffffffffu, s, o);
        d += __shfl_down_sync(0xffffffffu, d, o);
    }
    if (!lane) { g_as2[w] = s; g_ad2[w] = d; }
}

// ---------------- conv1 softmax numerator + denominator ----------------
__global__ void edge_ab1_k(const int* __restrict__ ei) {
    int e = blockIdx.x * blockDim.x + threadIdx.x;
    if (e >= ET) return;
    int s, d;
    if (e < EE) { s = ei[e]; d = ei[EE + e]; } else { s = d = e - EE; }
    float4 a = *(const float4*)(g_as1 + s * 4);
    float4 b = *(const float4*)(g_ad1 + d * 4);
    float ex = expf(lrelu(a.x + b.x));
    float ey = expf(lrelu(a.y + b.y));
    float ez = expf(lrelu(a.z + b.z));
    float ew = expf(lrelu(a.w + b.w));
    *(float4*)(g_e1 + (size_t)e * 4) = make_float4(ex, ey, ez, ew);
    red_add_v4(g_den1 + d * 4, ex, ey, ez, ew);
}

// ---------------- conv1 weighted aggregation (warp per edge) ----------------
__global__ void edge_c1_k(const int* __restrict__ ei) {
    int g = blockIdx.x * blockDim.x + threadIdx.x;
    int e = g >> 5, lane = g & 31;
    if (e >= ET) return;
    int s, d;
    if (e < EE) { s = ei[e]; d = ei[EE + e]; } else { s = d = e - EE; }
    float4 ev = *(const float4*)(g_e1 + (size_t)e * 4);
    float4 dn = *(const float4*)(g_den1 + d * 4);
    float wv[4] = { ev.x / (dn.x + 1e-16f), ev.y / (dn.y + 1e-16f),
                    ev.z / (dn.z + 1e-16f), ev.w / (dn.w + 1e-16f) };
    const float* hp = g_h1 + (size_t)s * F1;
    float* op = g_out1 + (size_t)d * F1;
#pragma unroll
    for (int i = 0; i < 2; i++) {
        int c = lane * 4 + i * 128;          // 128 cols per iter, same head per float4
        float w = wv[c >> 6];
        float4 hv = *(const float4*)(hp + c);
        red_add_v4(op + c, w * hv.x, w * hv.y, w * hv.z, w * hv.w);
    }
}

// ---------------- conv1 bias + relu (in place: out1 -> z) ----------------
__global__ void bias_relu1_k(const float* __restrict__ b1) {
    int i = blockIdx.x * blockDim.x + threadIdx.x;
    if (i >= NN * F1) return;
    float v = g_out1[i] + b1[i & (F1 - 1)];
    g_out1[i] = v > 0.f ? v : 0.f;
}

// ---------------- conv2 softmax ----------------
__global__ void edge_ab2_k(const int* __restrict__ ei) {
    int e = blockIdx.x * blockDim.x + threadIdx.x;
    if (e >= ET) return;
    int s, d;
    if (e < EE) { s = ei[e]; d = ei[EE + e]; } else { s = d = e - EE; }
    float ex = expf(lrelu(g_as2[s] + g_ad2[d]));
    g_e2[e] = ex;
    atomicAdd(g_den2 + d, ex);
}

// ---------------- conv2 aggregation (warp per edge, 64 cols) ----------------
__global__ void edge_c2_k(const int* __restrict__ ei) {
    int g = blockIdx.x * blockDim.x + threadIdx.x;
    int e = g >> 5, lane = g & 31;
    if (e >= ET) return;
    int s, d;
    if (e < EE) { s = ei[e]; d = ei[EE + e]; } else { s = d = e - EE; }
    float w = g_e2[e] / (g_den2[d] + 1e-16f);
    const float* hp = g_h2 + (size_t)s * OUTC;
    float* op = g_out2 + (size_t)d * OUTC;
    int c = lane * 2;
    float2 hv = *(const float2*)(hp + c);
    red_add_v2(op + c, w * hv.x, w * hv.y);
}

// ---------------- conv2 bias (in place: out2 -> z2) ----------------
__global__ void bias2_k(const float* __restrict__ b2) {
    int i = blockIdx.x * blockDim.x + threadIdx.x;
    if (i >= NN * OUTC) return;
    g_out2[i] += b2[i & (OUTC - 1)];
}

// ---------------- decode: logits over pos+neg edges (warp per edge) ----------------
__global__ void decode_k(const int* __restrict__ pos, const int* __restrict__ neg,
                         float* __restrict__ out) {
    int g = blockIdx.x * blockDim.x + threadIdx.x;
    int e = g >> 5, lane = g & 31;
    if (e >= 2 * EE) return;
    int a, b;
    if (e < EE) { a = pos[e]; b = pos[EE + e]; }
    else        { int t = e - EE; a = neg[t]; b = neg[EE + t]; }
    const float* za = g_out2 + (size_t)a * OUTC;
    const float* zb = g_out2 + (size_t)b * OUTC;
    float acc = 0.f;
#pragma unroll
    for (int i = 0; i < 2; i++) {
        int c = lane + i * 32;
        acc += za[c] * zb[c];
    }
#pragma unroll
    for (int o = 16; o; o >>= 1) acc += __shfl_down_sync(0xffffffffu, acc, o);
    if (!lane) out[e] = acc;
}

// ---------------- launch ----------------
extern "C" void kernel_launch(void* const* d_in, const int* in_sizes, int n_in,
                              void* d_out, int out_size) {
    const float* x    = (const float*)d_in[0];
    const int*   pos  = (const int*)d_in[1];
    const int*   neg  = (const int*)d_in[2];
    const float* W1   = (const float*)d_in[3];
    const float* as1v = (const float*)d_in[4];
    const float* ad1v = (const float*)d_in[5];
    const float* b1   = (const float*)d_in[6];
    const float* W2   = (const float*)d_in[7];
    const float* as2v = (const float*)d_in[8];
    const float* ad2v = (const float*)d_in[9];
    const float* b2   = (const float*)d_in[10];
    float* out = (float*)d_out;

    (void)in_sizes; (void)n_in; (void)out_size;

    zero_k<<<2048, 256>>>();

    // conv1
    sgemm_k<0><<<dim3(F1 / 64, (NN + 63) / 64), 256>>>(x, W1, NN, F1, INC);
    attn1_k<<<(NN * 32 + 255) / 256, 256>>>(as1v, ad1v);
    edge_ab1_k<<<(ET + 255) / 256, 256>>>(pos);
    edge_c1_k<<<(ET * 32 + 255) / 256, 256>>>(pos);
    bias_relu1_k<<<(NN * F1 + 255) / 256, 256>>>(b1);

    // conv2
    sgemm_k<1><<<dim3(OUTC / 64, (NN + 63) / 64), 256>>>(nullptr, W2, NN, OUTC, F1);
    attn2_k<<<(NN * 32 + 255) / 256, 256>>>(as2v, ad2v);
    edge_ab2_k<<<(ET + 255) / 256, 256>>>(pos);
    edge_c2_k<<<(ET * 32 + 255) / 256, 256>>>(pos);
    bias2_k<<<(NN * OUTC + 255) / 256, 256>>>(b2);

    // decode
    decode_k<<<(2 * EE * 32 + 255) / 256, 256>>>(pos, neg, out);
}

// round 4
// speedup vs baseline: 1.4619x; 1.4619x over previous
#include <cuda_runtime.h>
#include <math.h>

#define NN    50000
#define EE    800000
#define INC   128
#define HIDC  64
#define NH    4
#define OUTC  64
#define F1    (NH * HIDC)        // 256
#define ET    (EE + NN)          // edges + self loops = 850000

// ---------------- scratch (device globals; no allocation) ----------------
__device__ float g_h1  [(size_t)NN * F1];    // x @ W1
__device__ float g_out1[(size_t)NN * F1];    // conv1 out (= z, gemm2 input)
__device__ float g_as1 [NN * NH];
__device__ float g_ad1 [NN * NH];
__device__ float g_e1  [(size_t)ET * NH];    // exp(alpha) per CSR slot
__device__ float g_h2  [(size_t)NN * OUTC];  // z @ W2
__device__ float g_out2[(size_t)NN * OUTC];  // conv2 out (= z2)
__device__ float g_as2 [NN];
__device__ float g_ad2 [NN];
__device__ float g_e2  [ET];
// CSR by destination (shared by both conv layers)
__device__ int   g_off [NN + 1];
__device__ int   g_fill[NN];
__device__ int   g_srcidx[ET];

__device__ __forceinline__ float lrelu(float v) { return v > 0.f ? v : 0.2f * v; }

// ---------------- CSR build ----------------
__global__ void init_off_k() {
    int i = blockIdx.x * blockDim.x + threadIdx.x;
    if (i <= NN) g_off[i] = (i == 0) ? 0 : 1;   // each node has 1 self loop
}

__global__ void hist_k(const int* __restrict__ ei) {
    int e = blockIdx.x * blockDim.x + threadIdx.x;
    if (e >= EE) return;
    atomicAdd(&g_off[ei[EE + e] + 1], 1);
}

// single-block inclusive scan over g_off[0..NN]  ->  g_off[i] = start of node i
__global__ void scan_k() {
    __shared__ int sh[1024];
    __shared__ int carry;
    const int L = NN + 1;
    int tid = threadIdx.x;
    if (tid == 0) carry = 0;
    __syncthreads();
    for (int base = 0; base < L; base += 1024) {
        int i = base + tid;
        int v = (i < L) ? g_off[i] : 0;
        sh[tid] = v;
        __syncthreads();
#pragma unroll
        for (int o = 1; o < 1024; o <<= 1) {
            int t = (tid >= o) ? sh[tid - o] : 0;
            __syncthreads();
            sh[tid] += t;
            __syncthreads();
        }
        int prev = carry;
        __syncthreads();
        if (tid == 1023) carry = prev + sh[1023];
        if (i < L) {
            int res = sh[tid] + prev;
            g_off[i] = res;
            if (i < NN) g_fill[i] = res;
        }
        __syncthreads();
    }
}

__global__ void scatter_k(const int* __restrict__ ei) {
    int e = blockIdx.x * blockDim.x + threadIdx.x;
    if (e >= ET) return;
    int s, d;
    if (e < EE) { s = ei[e]; d = ei[EE + e]; } else { s = d = e - EE; }
    int p = atomicAdd(&g_fill[d], 1);
    g_srcidx[p] = s;
}

// ---------------- SGEMM: C[M,N] = A[M,K] @ B[K,N]  (128x64 tile, 8x4 micro) --
template <int MODE>
__global__ __launch_bounds__(256) void sgemm_k(const float* __restrict__ Aext,
                                               const float* __restrict__ B,
                                               int M, int N, int K) {
    const float* __restrict__ A = (MODE == 0) ? Aext : g_out1;
    float* __restrict__ C = (MODE == 0) ? g_h1 : g_h2;
    constexpr int BM = 128, BN = 64, BK = 16, TM = 8, TN = 4;

    __shared__ __align__(16) float As[BK][BM];
    __shared__ __align__(16) float Bs[BK][BN];

    int tid = threadIdx.x;
    int tr = tid >> 4, tc = tid & 15;          // 16x16 thread grid
    int rowBase = blockIdx.y * BM, colBase = blockIdx.x * BN;
    float acc[TM][TN] = {};

    int am = tid >> 1, ak = (tid & 1) * 8;     // A: 2 threads per row, 8 k each
    int bk = tid >> 4, bn = (tid & 15) * 4;    // B: 1 float4 per thread

    for (int k0 = 0; k0 < K; k0 += BK) {
        int gm = rowBase + am;
        float4 a0, a1;
        if (gm < M) {
            const float* ap = A + (size_t)gm * K + k0 + ak;
            a0 = *(const float4*)ap;
            a1 = *(const float4*)(ap + 4);
        } else {
            a0 = a1 = make_float4(0.f, 0.f, 0.f, 0.f);
        }
        As[ak + 0][am] = a0.x; As[ak + 1][am] = a0.y;
        As[ak + 2][am] = a0.z; As[ak + 3][am] = a0.w;
        As[ak + 4][am] = a1.x; As[ak + 5][am] = a1.y;
        As[ak + 6][am] = a1.z; As[ak + 7][am] = a1.w;

        float4 b4 = *(const float4*)(B + (size_t)(k0 + bk) * N + colBase + bn);
        *(float4*)&Bs[bk][bn] = b4;
        __syncthreads();

#pragma unroll
        for (int kk = 0; kk < BK; kk++) {
            float4 x0 = *(const float4*)&As[kk][tr * TM];
            float4 x1 = *(const float4*)&As[kk][tr * TM + 4];
            float4 y  = *(const float4*)&Bs[kk][tc * TN];
            float av[TM] = {x0.x, x0.y, x0.z, x0.w, x1.x, x1.y, x1.z, x1.w};
            float bv[TN] = {y.x, y.y, y.z, y.w};
#pragma unroll
            for (int i = 0; i < TM; i++)
#pragma unroll
                for (int j = 0; j < TN; j++) acc[i][j] += av[i] * bv[j];
        }
        __syncthreads();
    }
#pragma unroll
    for (int i = 0; i < TM; i++) {
        int gm = rowBase + tr * TM + i;
        if (gm < M) {
            float4 v = make_float4(acc[i][0], acc[i][1], acc[i][2], acc[i][3]);
            *(float4*)&C[(size_t)gm * N + colBase + tc * TN] = v;
        }
    }
}

// ---------------- attention dot products ----------------
__global__ void attn1_k(const float* __restrict__ att_s, const float* __restrict__ att_d) {
    int g = blockIdx.x * blockDim.x + threadIdx.x;
    int w = g >> 5, lane = g & 31;
    if (w >= NN) return;
    const float* hp = g_h1 + (size_t)w * F1;
#pragma unroll
    for (int hh = 0; hh < NH; hh++) {
        float s = 0.f, d = 0.f;
#pragma unroll
        for (int i = 0; i < 2; i++) {
            int cc = hh * 64 + lane + i * 32;
            float v = hp[cc];
            s += v * att_s[cc];
            d += v * att_d[cc];
        }
#pragma unroll
        for (int o = 16; o; o >>= 1) {
            s += __shfl_down_sync(0xffffffffu, s, o);
            d += __shfl_down_sync(0xffffffffu, d, o);
        }
        if (!lane) { g_as1[w * NH + hh] = s; g_ad1[w * NH + hh] = d; }
    }
}

__global__ void attn2_k(const float* __restrict__ att_s, const float* __restrict__ att_d) {
    int g = blockIdx.x * blockDim.x + threadIdx.x;
    int w = g >> 5, lane = g & 31;
    if (w >= NN) return;
    const float* hp = g_h2 + (size_t)w * OUTC;
    float s = 0.f, d = 0.f;
#pragma unroll
    for (int i = 0; i < 2; i++) {
        int cc = lane + i * 32;
        float v = hp[cc];
        s += v * att_s[cc];
        d += v * att_d[cc];
    }
#pragma unroll
    for (int o = 16; o; o >>= 1) {
        s += __shfl_down_sync(0xffffffffu, s, o);
        d += __shfl_down_sync(0xffffffffu, d, o);
    }
    if (!lane) { g_as2[w] = s; g_ad2[w] = d; }
}

// ---------------- conv1: per-node softmax + aggregation (warp per node) ------
__global__ __launch_bounds__(256) void agg1_k(const float* __restrict__ b1) {
    int g = blockIdx.x * blockDim.x + threadIdx.x;
    int node = g >> 5, lane = g & 31;
    if (node >= NN) return;
    int beg = g_off[node], end = g_off[node + 1];

    float4 ad = *(const float4*)(g_ad1 + node * 4);
    float d0 = 0.f, d1 = 0.f, d2 = 0.f, d3 = 0.f;
    for (int k = beg + lane; k < end; k += 32) {
        int j = g_srcidx[k];
        float4 as = *(const float4*)(g_as1 + j * 4);
        float e0 = __expf(lrelu(as.x + ad.x));
        float e1 = __expf(lrelu(as.y + ad.y));
        float e2 = __expf(lrelu(as.z + ad.z));
        float e3 = __expf(lrelu(as.w + ad.w));
        *(float4*)(g_e1 + (size_t)k * 4) = make_float4(e0, e1, e2, e3);
        d0 += e0; d1 += e1; d2 += e2; d3 += e3;
    }
#pragma unroll
    for (int o = 16; o; o >>= 1) {
        d0 += __shfl_xor_sync(0xffffffffu, d0, o);
        d1 += __shfl_xor_sync(0xffffffffu, d1, o);
        d2 += __shfl_xor_sync(0xffffffffu, d2, o);
        d3 += __shfl_xor_sync(0xffffffffu, d3, o);
    }
    float i0 = 1.f / (d0 + 1e-16f), i1 = 1.f / (d1 + 1e-16f);
    float i2 = 1.f / (d2 + 1e-16f), i3 = 1.f / (d3 + 1e-16f);

    float a0 = 0.f, a1 = 0.f, a2 = 0.f, a3 = 0.f;
    float a4 = 0.f, a5 = 0.f, a6 = 0.f, a7 = 0.f;
    int cA = lane * 4, cB = 128 + lane * 4;
    for (int k = beg; k < end; k++) {
        int j = g_srcidx[k];                               // broadcast load
        float4 ev = *(const float4*)(g_e1 + (size_t)k * 4);// broadcast load
        float wA = (lane < 16) ? ev.x * i0 : ev.y * i1;    // head 0/1 on cols 0..127
        float wB = (lane < 16) ? ev.z * i2 : ev.w * i3;    // head 2/3 on cols 128..255
        const float* hp = g_h1 + (size_t)j * F1;
        float4 hA = *(const float4*)(hp + cA);
        float4 hB = *(const float4*)(hp + cB);
        a0 += wA * hA.x; a1 += wA * hA.y; a2 += wA * hA.z; a3 += wA * hA.w;
        a4 += wB * hB.x; a5 += wB * hB.y; a6 += wB * hB.z; a7 += wB * hB.w;
    }
    float* op = g_out1 + (size_t)node * F1;
    float4 bA = *(const float4*)(b1 + cA);
    float4 bB = *(const float4*)(b1 + cB);
    float4 oA = make_float4(fmaxf(a0 + bA.x, 0.f), fmaxf(a1 + bA.y, 0.f),
                            fmaxf(a2 + bA.z, 0.f), fmaxf(a3 + bA.w, 0.f));
    float4 oB = make_float4(fmaxf(a4 + bB.x, 0.f), fmaxf(a5 + bB.y, 0.f),
                            fmaxf(a6 + bB.z, 0.f), fmaxf(a7 + bB.w, 0.f));
    *(float4*)(op + cA) = oA;
    *(float4*)(op + cB) = oB;
}

// ---------------- conv2: per-node softmax + aggregation (warp per node) ------
__global__ __launch_bounds__(256) void agg2_k(const float* __restrict__ b2) {
    int g = blockIdx.x * blockDim.x + threadIdx.x;
    int node = g >> 5, lane = g & 31;
    if (node >= NN) return;
    int beg = g_off[node], end = g_off[node + 1];

    float ad = g_ad2[node];
    float den = 0.f;
    for (int k = beg + lane; k < end; k += 32) {
        int j = g_srcidx[k];
        float e = __expf(lrelu(g_as2[j] + ad));
        g_e2[k] = e;
        den += e;
    }
#pragma unroll
    for (int o = 16; o; o >>= 1) den += __shfl_xor_sync(0xffffffffu, den, o);
    float inv = 1.f / (den + 1e-16f);

    float a0 = 0.f, a1 = 0.f;
    int c = lane * 2;
    for (int k = beg; k < end; k++) {
        int j = g_srcidx[k];                 // broadcast
        float w = g_e2[k] * inv;             // broadcast
        float2 hv = *(const float2*)(g_h2 + (size_t)j * OUTC + c);
        a0 += w * hv.x; a1 += w * hv.y;
    }
    float2 bb = *(const float2*)(b2 + c);
    float2 ov = make_float2(a0 + bb.x, a1 + bb.y);
    *(float2*)(g_out2 + (size_t)node * OUTC + c) = ov;
}

// ---------------- decode: logits over pos+neg edges (warp per edge) ----------
__global__ void decode_k(const int* __restrict__ pos, const int* __restrict__ neg,
                         float* __restrict__ out) {
    int g = blockIdx.x * blockDim.x + threadIdx.x;
    int e = g >> 5, lane = g & 31;
    if (e >= 2 * EE) return;
    int a, b;
    if (e < EE) { a = pos[e]; b = pos[EE + e]; }
    else        { int t = e - EE; a = neg[t]; b = neg[EE + t]; }
    const float* za = g_out2 + (size_t)a * OUTC;
    const float* zb = g_out2 + (size_t)b * OUTC;
    float acc = 0.f;
#pragma unroll
    for (int i = 0; i < 2; i++) {
        int c = lane + i * 32;
        acc += za[c] * zb[c];
    }
#pragma unroll
    for (int o = 16; o; o >>= 1) acc += __shfl_down_sync(0xffffffffu, acc, o);
    if (!lane) out[e] = acc;
}

// ---------------- launch ----------------
extern "C" void kernel_launch(void* const* d_in, const int* in_sizes, int n_in,
                              void* d_out, int out_size) {
    const float* x    = (const float*)d_in[0];
    const int*   pos  = (const int*)d_in[1];
    const int*   neg  = (const int*)d_in[2];
    const float* W1   = (const float*)d_in[3];
    const float* as1v = (const float*)d_in[4];
    const float* ad1v = (const float*)d_in[5];
    const float* b1   = (const float*)d_in[6];
    const float* W2   = (const float*)d_in[7];
    const float* as2v = (const float*)d_in[8];
    const float* ad2v = (const float*)d_in[9];
    const float* b2   = (const float*)d_in[10];
    float* out = (float*)d_out;
    (void)in_sizes; (void)n_in; (void)out_size;

    // CSR build (shared by both layers)
    init_off_k<<<(NN + 256) / 256, 256>>>();
    hist_k<<<(EE + 255) / 256, 256>>>(pos);
    scan_k<<<1, 1024>>>();
    scatter_k<<<(ET + 255) / 256, 256>>>(pos);

    // conv1
    sgemm_k<0><<<dim3(F1 / 64, (NN + 127) / 128), 256>>>(x, W1, NN, F1, INC);
    attn1_k<<<(NN * 32 + 255) / 256, 256>>>(as1v, ad1v);
    agg1_k<<<(NN * 32 + 255) / 256, 256>>>(b1);

    // conv2
    sgemm_k<1><<<dim3(OUTC / 64, (NN + 127) / 128), 256>>>(nullptr, W2, NN, OUTC, F1);
    attn2_k<<<(NN * 32 + 255) / 256, 256>>>(as2v, ad2v);
    agg2_k<<<(NN * 32 + 255) / 256, 256>>>(b2);

    // decode
    decode_k<<<(2 * EE * 32 + 255) / 256, 256>>>(pos, neg, out);
}

// round 5
// speedup vs baseline: 1.5023x; 1.0276x over previous
#include <cuda_runtime.h>
#include <math.h>
#include <stdint.h>

#define NN    50000
#define EE    800000
#define INC   128
#define HIDC  64
#define NH    4
#define OUTC  64
#define F1    (NH * HIDC)        // 256
#define ET    (EE + NN)          // edges + self loops = 850000

// ---------------- scratch (device globals; no allocation) ----------------
__device__ float g_h1  [(size_t)NN * F1];    // x @ W1
__device__ float g_out1[(size_t)NN * F1];    // conv1 out (= z, gemm2 input)
__device__ float g_as1 [NN * NH];
__device__ float g_ad1 [NN * NH];
__device__ float g_e1  [(size_t)ET * NH];    // exp(alpha) per CSR slot
__device__ float g_h2  [(size_t)NN * OUTC];  // z @ W2
__device__ float g_out2[(size_t)NN * OUTC];  // conv2 out (= z2)
__device__ float g_as2 [NN];
__device__ float g_ad2 [NN];
__device__ float g_e2  [ET];
// CSR by destination (shared by both conv layers)
__device__ int   g_off [NN + 1];
__device__ int   g_fill[NN];
__device__ int   g_srcidx[ET];

__device__ __forceinline__ float lrelu(float v) { return v > 0.f ? v : 0.2f * v; }

// ---------------- CSR build ----------------
__global__ void init_off_k() {
    int i = blockIdx.x * blockDim.x + threadIdx.x;
    if (i <= NN) g_off[i] = (i == 0) ? 0 : 1;   // each node has 1 self loop
}

__global__ void hist_k(const int* __restrict__ ei) {
    int e = blockIdx.x * blockDim.x + threadIdx.x;
    if (e >= EE) return;
    atomicAdd(&g_off[ei[EE + e] + 1], 1);
}

// single-block 3-phase inclusive scan over g_off[0..NN]
__global__ void scan_k() {
    const int L = NN + 1;
    const int CH = (L + 1023) / 1024;           // 49 elems per thread
    __shared__ int wsum[32];
    int t = threadIdx.x, lane = t & 31, wid = t >> 5;
    int beg = t * CH;
    int end = beg + CH; if (end > L) end = L;

    int s = 0;
    for (int i = beg; i < end; i++) s += g_off[i];

    int incl = s;
#pragma unroll
    for (int o = 1; o < 32; o <<= 1) {
        int v = __shfl_up_sync(0xffffffffu, incl, o);
        if (lane >= o) incl += v;
    }
    if (lane == 31) wsum[wid] = incl;
    __syncthreads();
    if (wid == 0) {
        int w = wsum[lane];
        int wi = w;
#pragma unroll
        for (int o = 1; o < 32; o <<= 1) {
            int v = __shfl_up_sync(0xffffffffu, wi, o);
            if (lane >= o) wi += v;
        }
        wsum[lane] = wi - w;                     // exclusive warp prefix
    }
    __syncthreads();

    int run = (incl - s) + wsum[wid];            // exclusive prefix for this thread
    for (int i = beg; i < end; i++) {
        run += g_off[i];
        g_off[i] = run;
        if (i < NN) g_fill[i] = run;
    }
}

__global__ void scatter_k(const int* __restrict__ ei) {
    int e = blockIdx.x * blockDim.x + threadIdx.x;
    if (e >= ET) return;
    int s, d;
    if (e < EE) { s = ei[e]; d = ei[EE + e]; } else { s = d = e - EE; }
    int p = atomicAdd(&g_fill[d], 1);
    g_srcidx[p] = s;
}

// ---------------- TF32 tensor-core GEMM (3xTF32 split, ~fp32 accuracy) ------
// C[M,N] = A[M,K] @ B[K,N]; BM=128, BN=64, BK=32; 8 warps, each 32x32.
__device__ __forceinline__ void split_tf32(float x, uint32_t& hi, uint32_t& lo) {
    uint32_t h;
    asm("cvt.rna.tf32.f32 %0, %1;" : "=r"(h) : "f"(x));
    float l = x - __uint_as_float(h);
    asm("cvt.rna.tf32.f32 %0, %1;" : "=r"(lo) : "f"(l));
    hi = h;
}
__device__ __forceinline__ void mma_tf32(float* d, const uint32_t* a, const uint32_t* b) {
    asm volatile(
        "mma.sync.aligned.m16n8k8.row.col.f32.tf32.tf32.f32 "
        "{%0,%1,%2,%3}, {%4,%5,%6,%7}, {%8,%9}, {%0,%1,%2,%3};\n"
        : "+f"(d[0]), "+f"(d[1]), "+f"(d[2]), "+f"(d[3])
        : "r"(a[0]), "r"(a[1]), "r"(a[2]), "r"(a[3]), "r"(b[0]), "r"(b[1]));
}

template <int MODE>
__global__ __launch_bounds__(256) void mma_gemm_k(const float* __restrict__ Aext,
                                                  const float* __restrict__ B,
                                                  int M, int N, int K) {
    const float* __restrict__ A = (MODE == 0) ? Aext : g_out1;
    float* __restrict__ C = (MODE == 0) ? g_h1 : g_h2;

    // padded strides chosen for conflict-free fragment reads
    __shared__ __align__(16) float As[128 * 36];   // [row][k], stride 36
    __shared__ __align__(16) float Bs[32 * 72];    // [k][n],  stride 72

    int tid = threadIdx.x;
    int wid = tid >> 5, lane = tid & 31;
    int warp_m = wid >> 1, warp_n = wid & 1;
    int m_warp = warp_m * 32, n_warp = warp_n * 32;
    int g = lane >> 2, c = lane & 3;
    int rowBase = blockIdx.y * 128, colBase = blockIdx.x * 64;

    float acc[2][4][4] = {};

    for (int k0 = 0; k0 < K; k0 += 32) {
        // stage A tile: 128 rows x 32 k
#pragma unroll
        for (int i = 0; i < 4; i++) {
            int fid = tid + i * 256;
            int row = fid >> 3, kq = (fid & 7) * 4;
            int gm = rowBase + row;
            float4 v = make_float4(0.f, 0.f, 0.f, 0.f);
            if (gm < M) v = *(const float4*)(A + (size_t)gm * K + k0 + kq);
            *(float4*)&As[row * 36 + kq] = v;
        }
        // stage B tile: 32 k x 64 n
#pragma unroll
        for (int i = 0; i < 2; i++) {
            int fid = tid + i * 256;
            int kr = fid >> 4, nq = (fid & 15) * 4;
            float4 v = *(const float4*)(B + (size_t)(k0 + kr) * N + colBase + nq);
            *(float4*)&Bs[kr * 72 + nq] = v;
        }
        __syncthreads();

#pragma unroll
        for (int ks = 0; ks < 32; ks += 8) {
            uint32_t ah[2][4], al[2][4], bh[4][2], bl[4][2];
#pragma unroll
            for (int t = 0; t < 2; t++) {
                int r0 = (m_warp + t * 16 + g) * 36 + ks + c;
                int r1 = r0 + 8 * 36;
                split_tf32(As[r0],     ah[t][0], al[t][0]);
                split_tf32(As[r1],     ah[t][1], al[t][1]);
                split_tf32(As[r0 + 4], ah[t][2], al[t][2]);
                split_tf32(As[r1 + 4], ah[t][3], al[t][3]);
            }
#pragma unroll
            for (int j = 0; j < 4; j++) {
                int col = n_warp + j * 8 + g;
                split_tf32(Bs[(ks + c) * 72 + col],     bh[j][0], bl[j][0]);
                split_tf32(Bs[(ks + c + 4) * 72 + col], bh[j][1], bl[j][1]);
            }
#pragma unroll
            for (int t = 0; t < 2; t++)
#pragma unroll
                for (int j = 0; j < 4; j++) {
                    mma_tf32(acc[t][j], ah[t], bh[j]);   // hi*hi
                    mma_tf32(acc[t][j], ah[t], bl[j]);   // hi*lo
                    mma_tf32(acc[t][j], al[t], bh[j]);   // lo*hi
                }
        }
        __syncthreads();
    }

#pragma unroll
    for (int t = 0; t < 2; t++)
#pragma unroll
        for (int j = 0; j < 4; j++) {
            int r0 = rowBase + m_warp + t * 16 + g;
            int cc = colBase + n_warp + j * 8 + 2 * c;
            if (r0 < M)
                *(float2*)&C[(size_t)r0 * N + cc] = make_float2(acc[t][j][0], acc[t][j][1]);
            int r1 = r0 + 8;
            if (r1 < M)
                *(float2*)&C[(size_t)r1 * N + cc] = make_float2(acc[t][j][2], acc[t][j][3]);
        }
}

// ---------------- attention dot products ----------------
__global__ void attn1_k(const float* __restrict__ att_s, const float* __restrict__ att_d) {
    int g = blockIdx.x * blockDim.x + threadIdx.x;
    int w = g >> 5, lane = g & 31;
    if (w >= NN) return;
    const float* hp = g_h1 + (size_t)w * F1;
#pragma unroll
    for (int hh = 0; hh < NH; hh++) {
        float s = 0.f, d = 0.f;
#pragma unroll
        for (int i = 0; i < 2; i++) {
            int cc = hh * 64 + lane + i * 32;
            float v = hp[cc];
            s += v * att_s[cc];
            d += v * att_d[cc];
        }
#pragma unroll
        for (int o = 16; o; o >>= 1) {
            s += __shfl_down_sync(0xffffffffu, s, o);
            d += __shfl_down_sync(0xffffffffu, d, o);
        }
        if (!lane) { g_as1[w * NH + hh] = s; g_ad1[w * NH + hh] = d; }
    }
}

__global__ void attn2_k(const float* __restrict__ att_s, const float* __restrict__ att_d) {
    int g = blockIdx.x * blockDim.x + threadIdx.x;
    int w = g >> 5, lane = g & 31;
    if (w >= NN) return;
    const float* hp = g_h2 + (size_t)w * OUTC;
    float s = 0.f, d = 0.f;
#pragma unroll
    for (int i = 0; i < 2; i++) {
        int cc = lane + i * 32;
        float v = hp[cc];
        s += v * att_s[cc];
        d += v * att_d[cc];
    }
#pragma unroll
    for (int o = 16; o; o >>= 1) {
        s += __shfl_down_sync(0xffffffffu, s, o);
        d += __shfl_down_sync(0xffffffffu, d, o);
    }
    if (!lane) { g_as2[w] = s; g_ad2[w] = d; }
}

// ---------------- conv1: per-node softmax + aggregation (warp per node) ------
__global__ __launch_bounds__(256) void agg1_k(const float* __restrict__ b1) {
    int g = blockIdx.x * blockDim.x + threadIdx.x;
    int node = g >> 5, lane = g & 31;
    if (node >= NN) return;
    int beg = g_off[node], end = g_off[node + 1];

    float4 ad = *(const float4*)(g_ad1 + node * 4);
    float d0 = 0.f, d1 = 0.f, d2 = 0.f, d3 = 0.f;
    for (int k = beg + lane; k < end; k += 32) {
        int j = g_srcidx[k];
        float4 as = *(const float4*)(g_as1 + j * 4);
        float e0 = __expf(lrelu(as.x + ad.x));
        float e1 = __expf(lrelu(as.y + ad.y));
        float e2 = __expf(lrelu(as.z + ad.z));
        float e3 = __expf(lrelu(as.w + ad.w));
        *(float4*)(g_e1 + (size_t)k * 4) = make_float4(e0, e1, e2, e3);
        d0 += e0; d1 += e1; d2 += e2; d3 += e3;
    }
#pragma unroll
    for (int o = 16; o; o >>= 1) {
        d0 += __shfl_xor_sync(0xffffffffu, d0, o);
        d1 += __shfl_xor_sync(0xffffffffu, d1, o);
        d2 += __shfl_xor_sync(0xffffffffu, d2, o);
        d3 += __shfl_xor_sync(0xffffffffu, d3, o);
    }
    float i0 = 1.f / (d0 + 1e-16f), i1 = 1.f / (d1 + 1e-16f);
    float i2 = 1.f / (d2 + 1e-16f), i3 = 1.f / (d3 + 1e-16f);

    float a0 = 0.f, a1 = 0.f, a2 = 0.f, a3 = 0.f;
    float a4 = 0.f, a5 = 0.f, a6 = 0.f, a7 = 0.f;
    int cA = lane * 4, cB = 128 + lane * 4;
    for (int k = beg; k < end; k++) {
        int j = g_srcidx[k];                               // broadcast load
        float4 ev = *(const float4*)(g_e1 + (size_t)k * 4);// broadcast load
        float wA = (lane < 16) ? ev.x * i0 : ev.y * i1;    // head 0/1 on cols 0..127
        float wB = (lane < 16) ? ev.z * i2 : ev.w * i3;    // head 2/3 on cols 128..255
        const float* hp = g_h1 + (size_t)j * F1;
        float4 hA = *(const float4*)(hp + cA);
        float4 hB = *(const float4*)(hp + cB);
        a0 += wA * hA.x; a1 += wA * hA.y; a2 += wA * hA.z; a3 += wA * hA.w;
        a4 += wB * hB.x; a5 += wB * hB.y; a6 += wB * hB.z; a7 += wB * hB.w;
    }
    float* op = g_out1 + (size_t)node * F1;
    float4 bA = *(const float4*)(b1 + cA);
    float4 bB = *(const float4*)(b1 + cB);
    float4 oA = make_float4(fmaxf(a0 + bA.x, 0.f), fmaxf(a1 + bA.y, 0.f),
                            fmaxf(a2 + bA.z, 0.f), fmaxf(a3 + bA.w, 0.f));
    float4 oB = make_float4(fmaxf(a4 + bB.x, 0.f), fmaxf(a5 + bB.y, 0.f),
                            fmaxf(a6 + bB.z, 0.f), fmaxf(a7 + bB.w, 0.f));
    *(float4*)(op + cA) = oA;
    *(float4*)(op + cB) = oB;
}

// ---------------- conv2: per-node softmax + aggregation (warp per node) ------
__global__ __launch_bounds__(256) void agg2_k(const float* __restrict__ b2) {
    int g = blockIdx.x * blockDim.x + threadIdx.x;
    int node = g >> 5, lane = g & 31;
    if (node >= NN) return;
    int beg = g_off[node], end = g_off[node + 1];

    float ad = g_ad2[node];
    float den = 0.f;
    for (int k = beg + lane; k < end; k += 32) {
        int j = g_srcidx[k];
        float e = __expf(lrelu(g_as2[j] + ad));
        g_e2[k] = e;
        den += e;
    }
#pragma unroll
    for (int o = 16; o; o >>= 1) den += __shfl_xor_sync(0xffffffffu, den, o);
    float inv = 1.f / (den + 1e-16f);

    float a0 = 0.f, a1 = 0.f;
    int c = lane * 2;
    for (int k = beg; k < end; k++) {
        int j = g_srcidx[k];                 // broadcast
        float w = g_e2[k] * inv;             // broadcast
        float2 hv = *(const float2*)(g_h2 + (size_t)j * OUTC + c);
        a0 += w * hv.x; a1 += w * hv.y;
    }
    float2 bb = *(const float2*)(b2 + c);
    float2 ov = make_float2(a0 + bb.x, a1 + bb.y);
    *(float2*)(g_out2 + (size_t)node * OUTC + c) = ov;
}

// ---------------- decode: logits over pos+neg edges (warp per edge) ----------
__global__ void decode_k(const int* __restrict__ pos, const int* __restrict__ neg,
                         float* __restrict__ out) {
    int g = blockIdx.x * blockDim.x + threadIdx.x;
    int e = g >> 5, lane = g & 31;
    if (e >= 2 * EE) return;
    int a, b;
    if (e < EE) { a = pos[e]; b = pos[EE + e]; }
    else        { int t = e - EE; a = neg[t]; b = neg[EE + t]; }
    const float* za = g_out2 + (size_t)a * OUTC;
    const float* zb = g_out2 + (size_t)b * OUTC;
    float acc = 0.f;
#pragma unroll
    for (int i = 0; i < 2; i++) {
        int c = lane + i * 32;
        acc += za[c] * zb[c];
    }
#pragma unroll
    for (int o = 16; o; o >>= 1) acc += __shfl_down_sync(0xffffffffu, acc, o);
    if (!lane) out[e] = acc;
}

// ---------------- launch ----------------
extern "C" void kernel_launch(void* const* d_in, const int* in_sizes, int n_in,
                              void* d_out, int out_size) {
    const float* x    = (const float*)d_in[0];
    const int*   pos  = (const int*)d_in[1];
    const int*   neg  = (const int*)d_in[2];
    const float* W1   = (const float*)d_in[3];
    const float* as1v = (const float*)d_in[4];
    const float* ad1v = (const float*)d_in[5];
    const float* b1   = (const float*)d_in[6];
    const float* W2   = (const float*)d_in[7];
    const float* as2v = (const float*)d_in[8];
    const float* ad2v = (const float*)d_in[9];
    const float* b2   = (const float*)d_in[10];
    float* out = (float*)d_out;
    (void)in_sizes; (void)n_in; (void)out_size;

    // CSR build (shared by both layers)
    init_off_k<<<(NN + 256) / 256, 256>>>();
    hist_k<<<(EE + 255) / 256, 256>>>(pos);
    scan_k<<<1, 1024>>>();
    scatter_k<<<(ET + 255) / 256, 256>>>(pos);

    // conv1
    mma_gemm_k<0><<<dim3(F1 / 64, (NN + 127) / 128), 256>>>(x, W1, NN, F1, INC);
    attn1_k<<<(NN * 32 + 255) / 256, 256>>>(as1v, ad1v);
    agg1_k<<<(NN * 32 + 255) / 256, 256>>>(b1);

    // conv2
    mma_gemm_k<1><<<dim3(OUTC / 64, (NN + 127) / 128), 256>>>(nullptr, W2, NN, OUTC, F1);
    attn2_k<<<(NN * 32 + 255) / 256, 256>>>(as2v, ad2v);
    agg2_k<<<(NN * 32 + 255) / 256, 256>>>(b2);

    // decode
    decode_k<<<(2 * EE * 32 + 255) / 256, 256>>>(pos, neg, out);
}

// round 6
// speedup vs baseline: 1.8456x; 1.2285x over previous
#include <cuda_runtime.h>
#include <math.h>
#include <stdint.h>

#define NN    50000
#define EE    800000
#define INC   128
#define HIDC  64
#define NH    4
#define OUTC  64
#define F1    (NH * HIDC)        // 256
#define ET    (EE + NN)          // edges + self loops = 850000

// ---------------- scratch (device globals; no allocation) ----------------
__device__ float g_h1  [(size_t)NN * F1];    // x @ W1
__device__ float g_out1[(size_t)NN * F1];    // conv1 out (= z, gemm2 input)
__device__ float g_as1 [NN * NH];
__device__ float g_ad1 [NN * NH];
__device__ float g_e1  [(size_t)ET * NH];    // exp(alpha) per CSR slot
__device__ float g_h2  [(size_t)NN * OUTC];  // z @ W2
__device__ float g_out2[(size_t)NN * OUTC];  // conv2 out (= z2)
__device__ float g_as2 [NN];
__device__ float g_ad2 [NN];
__device__ float g_e2  [ET];
// CSR by destination (shared by both conv layers)
__device__ int   g_off [NN + 1];
__device__ int   g_fill[NN];
__device__ int   g_srcidx[ET];

__device__ __forceinline__ float lrelu(float v) { return v > 0.f ? v : 0.2f * v; }

// ---------------- CSR build ----------------
__global__ void init_off_k() {
    int i = blockIdx.x * blockDim.x + threadIdx.x;
    if (i <= NN) g_off[i] = (i == 0) ? 0 : 1;   // each node has 1 self loop
}

__global__ void hist_k(const int* __restrict__ ei) {
    int e = blockIdx.x * blockDim.x + threadIdx.x;
    if (e >= EE) return;
    atomicAdd(&g_off[ei[EE + e] + 1], 1);
}

// single-block 3-phase inclusive scan over g_off[0..NN]
__global__ void scan_k() {
    const int L = NN + 1;
    const int CH = (L + 1023) / 1024;
    __shared__ int wsum[32];
    int t = threadIdx.x, lane = t & 31, wid = t >> 5;
    int beg = t * CH;
    int end = beg + CH; if (end > L) end = L;

    int s = 0;
    for (int i = beg; i < end; i++) s += g_off[i];

    int incl = s;
#pragma unroll
    for (int o = 1; o < 32; o <<= 1) {
        int v = __shfl_up_sync(0xffffffffu, incl, o);
        if (lane >= o) incl += v;
    }
    if (lane == 31) wsum[wid] = incl;
    __syncthreads();
    if (wid == 0) {
        int w = wsum[lane];
        int wi = w;
#pragma unroll
        for (int o = 1; o < 32; o <<= 1) {
            int v = __shfl_up_sync(0xffffffffu, wi, o);
            if (lane >= o) wi += v;
        }
        wsum[lane] = wi - w;
    }
    __syncthreads();

    int run = (incl - s) + wsum[wid];
    for (int i = beg; i < end; i++) {
        run += g_off[i];
        g_off[i] = run;
        if (i < NN) g_fill[i] = run;
    }
}

__global__ void scatter_k(const int* __restrict__ ei) {
    int e = blockIdx.x * blockDim.x + threadIdx.x;
    if (e >= ET) return;
    int s, d;
    if (e < EE) { s = ei[e]; d = ei[EE + e]; } else { s = d = e - EE; }
    int p = atomicAdd(&g_fill[d], 1);
    g_srcidx[p] = s;
}

// ---------------- TF32 tensor-core GEMM (3xTF32 split) + fused attention ----
// C[M,N] = A[M,K] @ B[K,N]; BM=128, BN=64, BK=32; 8 warps, each 32x32.
// Epilogue also computes per-row attention dots over this block's 64 columns
// (for MODE 0, blockIdx.x == head; for MODE 1, single head covers all cols).
__device__ __forceinline__ void split_tf32(float x, uint32_t& hi, uint32_t& lo) {
    uint32_t h;
    asm("cvt.rna.tf32.f32 %0, %1;" : "=r"(h) : "f"(x));
    float l = x - __uint_as_float(h);
    asm("cvt.rna.tf32.f32 %0, %1;" : "=r"(lo) : "f"(l));
    hi = h;
}
__device__ __forceinline__ void mma_tf32(float* d, const uint32_t* a, const uint32_t* b) {
    asm volatile(
        "mma.sync.aligned.m16n8k8.row.col.f32.tf32.tf32.f32 "
        "{%0,%1,%2,%3}, {%4,%5,%6,%7}, {%8,%9}, {%0,%1,%2,%3};\n"
        : "+f"(d[0]), "+f"(d[1]), "+f"(d[2]), "+f"(d[3])
        : "r"(a[0]), "r"(a[1]), "r"(a[2]), "r"(a[3]), "r"(b[0]), "r"(b[1]));
}

template <int MODE>
__global__ __launch_bounds__(256) void mma_gemm_k(const float* __restrict__ Aext,
                                                  const float* __restrict__ B,
                                                  const float* __restrict__ att_s,
                                                  const float* __restrict__ att_d,
                                                  int M, int N, int K) {
    const float* __restrict__ A = (MODE == 0) ? Aext : g_out1;
    float* __restrict__ C = (MODE == 0) ? g_h1 : g_h2;

    __shared__ __align__(16) float As[128 * 36];   // [row][k], stride 36
    __shared__ __align__(16) float Bs[32 * 72];    // [k][n],  stride 72
    __shared__ float sAs[128], sAd[128];

    int tid = threadIdx.x;
    int wid = tid >> 5, lane = tid & 31;
    int warp_m = wid >> 1, warp_n = wid & 1;
    int m_warp = warp_m * 32, n_warp = warp_n * 32;
    int g = lane >> 2, c = lane & 3;
    int rowBase = blockIdx.y * 128, colBase = blockIdx.x * 64;

    if (tid < 128) { sAs[tid] = 0.f; sAd[tid] = 0.f; }

    float acc[2][4][4] = {};

    for (int k0 = 0; k0 < K; k0 += 32) {
#pragma unroll
        for (int i = 0; i < 4; i++) {
            int fid = tid + i * 256;
            int row = fid >> 3, kq = (fid & 7) * 4;
            int gm = rowBase + row;
            float4 v = make_float4(0.f, 0.f, 0.f, 0.f);
            if (gm < M) v = *(const float4*)(A + (size_t)gm * K + k0 + kq);
            *(float4*)&As[row * 36 + kq] = v;
        }
#pragma unroll
        for (int i = 0; i < 2; i++) {
            int fid = tid + i * 256;
            int kr = fid >> 4, nq = (fid & 15) * 4;
            float4 v = *(const float4*)(B + (size_t)(k0 + kr) * N + colBase + nq);
            *(float4*)&Bs[kr * 72 + nq] = v;
        }
        __syncthreads();

#pragma unroll
        for (int ks = 0; ks < 32; ks += 8) {
            uint32_t ah[2][4], al[2][4], bh[4][2], bl[4][2];
#pragma unroll
            for (int t = 0; t < 2; t++) {
                int r0 = (m_warp + t * 16 + g) * 36 + ks + c;
                int r1 = r0 + 8 * 36;
                split_tf32(As[r0],     ah[t][0], al[t][0]);
                split_tf32(As[r1],     ah[t][1], al[t][1]);
                split_tf32(As[r0 + 4], ah[t][2], al[t][2]);
                split_tf32(As[r1 + 4], ah[t][3], al[t][3]);
            }
#pragma unroll
            for (int j = 0; j < 4; j++) {
                int col = n_warp + j * 8 + g;
                split_tf32(Bs[(ks + c) * 72 + col],     bh[j][0], bl[j][0]);
                split_tf32(Bs[(ks + c + 4) * 72 + col], bh[j][1], bl[j][1]);
            }
#pragma unroll
            for (int t = 0; t < 2; t++)
#pragma unroll
                for (int j = 0; j < 4; j++) {
                    mma_tf32(acc[t][j], ah[t], bh[j]);
                    mma_tf32(acc[t][j], ah[t], bl[j]);
                    mma_tf32(acc[t][j], al[t], bh[j]);
                }
        }
        __syncthreads();
    }

    // write C
#pragma unroll
    for (int t = 0; t < 2; t++)
#pragma unroll
        for (int j = 0; j < 4; j++) {
            int r0 = rowBase + m_warp + t * 16 + g;
            int cc = colBase + n_warp + j * 8 + 2 * c;
            if (r0 < M)
                *(float2*)&C[(size_t)r0 * N + cc] = make_float2(acc[t][j][0], acc[t][j][1]);
            int r1 = r0 + 8;
            if (r1 < M)
                *(float2*)&C[(size_t)r1 * N + cc] = make_float2(acc[t][j][2], acc[t][j][3]);
        }

    // fused attention dots over this block's 64 columns
#pragma unroll
    for (int t = 0; t < 2; t++) {
        float s0 = 0.f, d0 = 0.f, s1 = 0.f, d1 = 0.f;
#pragma unroll
        for (int j = 0; j < 4; j++) {
            int cg = colBase + n_warp + j * 8 + 2 * c;
            float w0 = __ldg(att_s + cg), w1 = __ldg(att_s + cg + 1);
            float v0 = __ldg(att_d + cg), v1 = __ldg(att_d + cg + 1);
            s0 += acc[t][j][0] * w0 + acc[t][j][1] * w1;
            d0 += acc[t][j][0] * v0 + acc[t][j][1] * v1;
            s1 += acc[t][j][2] * w0 + acc[t][j][3] * w1;
            d1 += acc[t][j][2] * v0 + acc[t][j][3] * v1;
        }
#pragma unroll
        for (int o = 1; o < 4; o <<= 1) {
            s0 += __shfl_xor_sync(0xffffffffu, s0, o);
            d0 += __shfl_xor_sync(0xffffffffu, d0, o);
            s1 += __shfl_xor_sync(0xffffffffu, s1, o);
            d1 += __shfl_xor_sync(0xffffffffu, d1, o);
        }
        if (c == 0) {
            int rl = m_warp + t * 16 + g;
            atomicAdd(&sAs[rl], s0);     atomicAdd(&sAd[rl], d0);
            atomicAdd(&sAs[rl + 8], s1); atomicAdd(&sAd[rl + 8], d1);
        }
    }
    __syncthreads();
    if (tid < 128) {
        int gm = rowBase + tid;
        if (gm < M) {
            if (MODE == 0) {
                g_as1[gm * NH + blockIdx.x] = sAs[tid];
                g_ad1[gm * NH + blockIdx.x] = sAd[tid];
            } else {
                g_as2[gm] = sAs[tid];
                g_ad2[gm] = sAd[tid];
            }
        }
    }
}

// ---------------- conv1: per-node softmax + aggregation (warp per node) ------
__global__ __launch_bounds__(256) void agg1_k(const float* __restrict__ b1) {
    int g = blockIdx.x * blockDim.x + threadIdx.x;
    int node = g >> 5, lane = g & 31;
    if (node >= NN) return;
    int beg = g_off[node], end = g_off[node + 1];

    float4 ad = *(const float4*)(g_ad1 + node * 4);
    float d0 = 0.f, d1 = 0.f, d2 = 0.f, d3 = 0.f;
    for (int k = beg + lane; k < end; k += 32) {
        int j = g_srcidx[k];
        float4 as = *(const float4*)(g_as1 + j * 4);
        float e0 = __expf(lrelu(as.x + ad.x));
        float e1 = __expf(lrelu(as.y + ad.y));
        float e2 = __expf(lrelu(as.z + ad.z));
        float e3 = __expf(lrelu(as.w + ad.w));
        *(float4*)(g_e1 + (size_t)k * 4) = make_float4(e0, e1, e2, e3);
        d0 += e0; d1 += e1; d2 += e2; d3 += e3;
    }
#pragma unroll
    for (int o = 16; o; o >>= 1) {
        d0 += __shfl_xor_sync(0xffffffffu, d0, o);
        d1 += __shfl_xor_sync(0xffffffffu, d1, o);
        d2 += __shfl_xor_sync(0xffffffffu, d2, o);
        d3 += __shfl_xor_sync(0xffffffffu, d3, o);
    }
    float i0 = 1.f / (d0 + 1e-16f), i1 = 1.f / (d1 + 1e-16f);
    float i2 = 1.f / (d2 + 1e-16f), i3 = 1.f / (d3 + 1e-16f);

    float a0 = 0.f, a1 = 0.f, a2 = 0.f, a3 = 0.f;
    float a4 = 0.f, a5 = 0.f, a6 = 0.f, a7 = 0.f;
    int cA = lane * 4, cB = 128 + lane * 4;
    for (int k = beg; k < end; k++) {
        int j = g_srcidx[k];
        float4 ev = *(const float4*)(g_e1 + (size_t)k * 4);
        float wA = (lane < 16) ? ev.x * i0 : ev.y * i1;
        float wB = (lane < 16) ? ev.z * i2 : ev.w * i3;
        const float* hp = g_h1 + (size_t)j * F1;
        float4 hA = *(const float4*)(hp + cA);
        float4 hB = *(const float4*)(hp + cB);
        a0 += wA * hA.x; a1 += wA * hA.y; a2 += wA * hA.z; a3 += wA * hA.w;
        a4 += wB * hB.x; a5 += wB * hB.y; a6 += wB * hB.z; a7 += wB * hB.w;
    }
    float* op = g_out1 + (size_t)node * F1;
    float4 bA = *(const float4*)(b1 + cA);
    float4 bB = *(const float4*)(b1 + cB);
    float4 oA = make_float4(fmaxf(a0 + bA.x, 0.f), fmaxf(a1 + bA.y, 0.f),
                            fmaxf(a2 + bA.z, 0.f), fmaxf(a3 + bA.w, 0.f));
    float4 oB = make_float4(fmaxf(a4 + bB.x, 0.f), fmaxf(a5 + bB.y, 0.f),
                            fmaxf(a6 + bB.z, 0.f), fmaxf(a7 + bB.w, 0.f));
    *(float4*)(op + cA) = oA;
    *(float4*)(op + cB) = oB;
}

// ---------------- conv2: per-node softmax + aggregation (warp per node) ------
__global__ __launch_bounds__(256) void agg2_k(const float* __restrict__ b2) {
    int g = blockIdx.x * blockDim.x + threadIdx.x;
    int node = g >> 5, lane = g & 31;
    if (node >= NN) return;
    int beg = g_off[node], end = g_off[node + 1];

    float ad = g_ad2[node];
    float den = 0.f;
    for (int k = beg + lane; k < end; k += 32) {
        int j = g_srcidx[k];
        float e = __expf(lrelu(g_as2[j] + ad));
        g_e2[k] = e;
        den += e;
    }
#pragma unroll
    for (int o = 16; o; o >>= 1) den += __shfl_xor_sync(0xffffffffu, den, o);
    float inv = 1.f / (den + 1e-16f);

    float a0 = 0.f, a1 = 0.f;
    int c = lane * 2;
    for (int k = beg; k < end; k++) {
        int j = g_srcidx[k];
        float w = g_e2[k] * inv;
        float2 hv = *(const float2*)(g_h2 + (size_t)j * OUTC + c);
        a0 += w * hv.x; a1 += w * hv.y;
    }
    float2 bb = *(const float2*)(b2 + c);
    float2 ov = make_float2(a0 + bb.x, a1 + bb.y);
    *(float2*)(g_out2 + (size_t)node * OUTC + c) = ov;
}

// ---------------- decode: logits (16 lanes per edge, 2 edges per warp) -------
__global__ void decode_k(const int* __restrict__ pos, const int* __restrict__ neg,
                         float* __restrict__ out) {
    int g = blockIdx.x * blockDim.x + threadIdx.x;
    int e = g >> 4, lane = g & 15;
    if (e >= 2 * EE) return;
    int a, b;
    if (e < EE) { a = pos[e]; b = pos[EE + e]; }
    else        { int t = e - EE; a = neg[t]; b = neg[EE + t]; }
    const float* za = g_out2 + (size_t)a * OUTC;
    const float* zb = g_out2 + (size_t)b * OUTC;
    int c = lane * 4;
    float4 va = *(const float4*)(za + c);
    float4 vb = *(const float4*)(zb + c);
    float acc = va.x * vb.x + va.y * vb.y + va.z * vb.z + va.w * vb.w;
#pragma unroll
    for (int o = 8; o; o >>= 1) acc += __shfl_xor_sync(0xffffffffu, acc, o);
    if (!lane) out[e] = acc;
}

// ---------------- launch ----------------
extern "C" void kernel_launch(void* const* d_in, const int* in_sizes, int n_in,
                              void* d_out, int out_size) {
    const float* x    = (const float*)d_in[0];
    const int*   pos  = (const int*)d_in[1];
    const int*   neg  = (const int*)d_in[2];
    const float* W1   = (const float*)d_in[3];
    const float* as1v = (const float*)d_in[4];
    const float* ad1v = (const float*)d_in[5];
    const float* b1   = (const float*)d_in[6];
    const float* W2   = (const float*)d_in[7];
    const float* as2v = (const float*)d_in[8];
    const float* ad2v = (const float*)d_in[9];
    const float* b2   = (const float*)d_in[10];
    float* out = (float*)d_out;
    (void)in_sizes; (void)n_in; (void)out_size;

    // one-time side stream + events (created on the uncaptured correctness run)
    static cudaStream_t s1 = nullptr;
    static cudaEvent_t evFork = nullptr, evJoin = nullptr;
    if (s1 == nullptr) {
        cudaStreamCreateWithFlags(&s1, cudaStreamNonBlocking);
        cudaEventCreateWithFlags(&evFork, cudaEventDisableTiming);
        cudaEventCreateWithFlags(&evJoin, cudaEventDisableTiming);
    }

    // fork: CSR build on s1, concurrent with gemm1 on the main stream
    cudaEventRecord(evFork, 0);
    cudaStreamWaitEvent(s1, evFork, 0);
    init_off_k<<<(NN + 256) / 256, 256, 0, s1>>>();
    hist_k<<<(EE + 255) / 256, 256, 0, s1>>>(pos);
    scan_k<<<1, 1024, 0, s1>>>();
    scatter_k<<<(ET + 255) / 256, 256, 0, s1>>>(pos);
    cudaEventRecord(evJoin, s1);

    // conv1 linear + fused attention dots (main stream)
    mma_gemm_k<0><<<dim3(F1 / 64, (NN + 127) / 128), 256>>>(x, W1, as1v, ad1v, NN, F1, INC);

    // join: aggregation needs both CSR and gemm1
    cudaStreamWaitEvent(0, evJoin, 0);
    agg1_k<<<(NN * 32 + 255) / 256, 256>>>(b1);

    // conv2
    mma_gemm_k<1><<<dim3(OUTC / 64, (NN + 127) / 128), 256>>>(nullptr, W2, as2v, ad2v, NN, OUTC, F1);
    agg2_k<<<(NN * 32 + 255) / 256, 256>>>(b2);

    // decode
    decode_k<<<(2 * EE * 16 + 255) / 256, 256>>>(pos, neg, out);
}

// round 7
// speedup vs baseline: 2.1112x; 1.1439x over previous
#include <cuda_runtime.h>
#include <cuda_fp16.h>
#include <math.h>
#include <stdint.h>

#define NN    50000
#define EE    800000
#define INC   128
#define HIDC  64
#define NH    4
#define OUTC  64
#define F1    (NH * HIDC)        // 256
#define ET    (EE + NN)          // edges + self loops = 850000

// ---------------- scratch (device globals; no allocation) ----------------
__device__ __half g_h1h [(size_t)NN * F1];   // x @ W1 (fp16 storage, fp32 compute)
__device__ float  g_out1[(size_t)NN * F1];   // conv1 out (= z, gemm2 input, fp32)
__device__ float  g_as1 [NN * NH];
__device__ float  g_ad1 [NN * NH];
__device__ float  g_e1  [(size_t)ET * NH];   // exp(alpha) per CSR slot
__device__ float  g_h2  [(size_t)NN * OUTC]; // z @ W2 (fp32)
__device__ __half g_out2h[(size_t)NN * OUTC];// z2 (fp16 storage; decode-only consumer)
__device__ float  g_as2 [NN];
__device__ float  g_ad2 [NN];
__device__ float  g_e2  [ET];
// CSR by destination (shared by both conv layers)
__device__ int    g_off [NN + 1];
__device__ int    g_fill[NN];
__device__ int    g_srcidx[ET];

__device__ __forceinline__ float lrelu(float v) { return v > 0.f ? v : 0.2f * v; }

// ---------------- CSR build ----------------
__global__ void init_off_k() {
    int i = blockIdx.x * blockDim.x + threadIdx.x;
    if (i <= NN) g_off[i] = (i == 0) ? 0 : 1;   // each node has 1 self loop
}

__global__ void hist_k(const int* __restrict__ ei) {
    int e = blockIdx.x * blockDim.x + threadIdx.x;
    if (e >= EE) return;
    atomicAdd(&g_off[ei[EE + e] + 1], 1);
}

// single-block 3-phase inclusive scan over g_off[0..NN]
__global__ void scan_k() {
    const int L = NN + 1;
    const int CH = (L + 1023) / 1024;
    __shared__ int wsum[32];
    int t = threadIdx.x, lane = t & 31, wid = t >> 5;
    int beg = t * CH;
    int end = beg + CH; if (end > L) end = L;

    int s = 0;
    for (int i = beg; i < end; i++) s += g_off[i];

    int incl = s;
#pragma unroll
    for (int o = 1; o < 32; o <<= 1) {
        int v = __shfl_up_sync(0xffffffffu, incl, o);
        if (lane >= o) incl += v;
    }
    if (lane == 31) wsum[wid] = incl;
    __syncthreads();
    if (wid == 0) {
        int w = wsum[lane];
        int wi = w;
#pragma unroll
        for (int o = 1; o < 32; o <<= 1) {
            int v = __shfl_up_sync(0xffffffffu, wi, o);
            if (lane >= o) wi += v;
        }
        wsum[lane] = wi - w;
    }
    __syncthreads();

    int run = (incl - s) + wsum[wid];
    for (int i = beg; i < end; i++) {
        run += g_off[i];
        g_off[i] = run;
        if (i < NN) g_fill[i] = run;
    }
}

__global__ void scatter_k(const int* __restrict__ ei) {
    int e = blockIdx.x * blockDim.x + threadIdx.x;
    if (e >= ET) return;
    int s, d;
    if (e < EE) { s = ei[e]; d = ei[EE + e]; } else { s = d = e - EE; }
    int p = atomicAdd(&g_fill[d], 1);
    g_srcidx[p] = s;
}

// ---------------- TF32 tensor-core GEMM (3xTF32 split) + fused attention ----
__device__ __forceinline__ void split_tf32(float x, uint32_t& hi, uint32_t& lo) {
    uint32_t h;
    asm("cvt.rna.tf32.f32 %0, %1;" : "=r"(h) : "f"(x));
    float l = x - __uint_as_float(h);
    asm("cvt.rna.tf32.f32 %0, %1;" : "=r"(lo) : "f"(l));
    hi = h;
}
__device__ __forceinline__ void mma_tf32(float* d, const uint32_t* a, const uint32_t* b) {
    asm volatile(
        "mma.sync.aligned.m16n8k8.row.col.f32.tf32.tf32.f32 "
        "{%0,%1,%2,%3}, {%4,%5,%6,%7}, {%8,%9}, {%0,%1,%2,%3};\n"
        : "+f"(d[0]), "+f"(d[1]), "+f"(d[2]), "+f"(d[3])
        : "r"(a[0]), "r"(a[1]), "r"(a[2]), "r"(a[3]), "r"(b[0]), "r"(b[1]));
}

// MODE 0: A = x (ext), C = g_h1h (fp16), attn -> g_as1/g_ad1 per head (blockIdx.x)
// MODE 1: A = g_out1,  C = g_h2 (fp32),  attn -> g_as2/g_ad2
template <int MODE>
__global__ __launch_bounds__(256) void mma_gemm_k(const float* __restrict__ Aext,
                                                  const float* __restrict__ B,
                                                  const float* __restrict__ att_s,
                                                  const float* __restrict__ att_d,
                                                  int M, int N, int K) {
    const float* __restrict__ A = (MODE == 0) ? Aext : g_out1;

    __shared__ __align__(16) float As[128 * 36];   // [row][k], stride 36
    __shared__ __align__(16) float Bs[32 * 72];    // [k][n],  stride 72
    __shared__ float sAs[128], sAd[128];

    int tid = threadIdx.x;
    int wid = tid >> 5, lane = tid & 31;
    int warp_m = wid >> 1, warp_n = wid & 1;
    int m_warp = warp_m * 32, n_warp = warp_n * 32;
    int g = lane >> 2, c = lane & 3;
    int rowBase = blockIdx.y * 128, colBase = blockIdx.x * 64;

    if (tid < 128) { sAs[tid] = 0.f; sAd[tid] = 0.f; }

    float acc[2][4][4] = {};

    for (int k0 = 0; k0 < K; k0 += 32) {
#pragma unroll
        for (int i = 0; i < 4; i++) {
            int fid = tid + i * 256;
            int row = fid >> 3, kq = (fid & 7) * 4;
            int gm = rowBase + row;
            float4 v = make_float4(0.f, 0.f, 0.f, 0.f);
            if (gm < M) v = *(const float4*)(A + (size_t)gm * K + k0 + kq);
            *(float4*)&As[row * 36 + kq] = v;
        }
#pragma unroll
        for (int i = 0; i < 2; i++) {
            int fid = tid + i * 256;
            int kr = fid >> 4, nq = (fid & 15) * 4;
            float4 v = *(const float4*)(B + (size_t)(k0 + kr) * N + colBase + nq);
            *(float4*)&Bs[kr * 72 + nq] = v;
        }
        __syncthreads();

#pragma unroll
        for (int ks = 0; ks < 32; ks += 8) {
            uint32_t ah[2][4], al[2][4], bh[4][2], bl[4][2];
#pragma unroll
            for (int t = 0; t < 2; t++) {
                int r0 = (m_warp + t * 16 + g) * 36 + ks + c;
                int r1 = r0 + 8 * 36;
                split_tf32(As[r0],     ah[t][0], al[t][0]);
                split_tf32(As[r1],     ah[t][1], al[t][1]);
                split_tf32(As[r0 + 4], ah[t][2], al[t][2]);
                split_tf32(As[r1 + 4], ah[t][3], al[t][3]);
            }
#pragma unroll
            for (int j = 0; j < 4; j++) {
                int col = n_warp + j * 8 + g;
                split_tf32(Bs[(ks + c) * 72 + col],     bh[j][0], bl[j][0]);
                split_tf32(Bs[(ks + c + 4) * 72 + col], bh[j][1], bl[j][1]);
            }
#pragma unroll
            for (int t = 0; t < 2; t++)
#pragma unroll
                for (int j = 0; j < 4; j++) {
                    mma_tf32(acc[t][j], ah[t], bh[j]);
                    mma_tf32(acc[t][j], ah[t], bl[j]);
                    mma_tf32(acc[t][j], al[t], bh[j]);
                }
        }
        __syncthreads();
    }

    // write C (fp16 for MODE 0, fp32 for MODE 1)
#pragma unroll
    for (int t = 0; t < 2; t++)
#pragma unroll
        for (int j = 0; j < 4; j++) {
            int r0 = rowBase + m_warp + t * 16 + g;
            int r1 = r0 + 8;
            int cc = colBase + n_warp + j * 8 + 2 * c;
            if (MODE == 0) {
                if (r0 < M)
                    *(__half2*)&g_h1h[(size_t)r0 * N + cc] =
                        __floats2half2_rn(acc[t][j][0], acc[t][j][1]);
                if (r1 < M)
                    *(__half2*)&g_h1h[(size_t)r1 * N + cc] =
                        __floats2half2_rn(acc[t][j][2], acc[t][j][3]);
            } else {
                if (r0 < M)
                    *(float2*)&g_h2[(size_t)r0 * N + cc] = make_float2(acc[t][j][0], acc[t][j][1]);
                if (r1 < M)
                    *(float2*)&g_h2[(size_t)r1 * N + cc] = make_float2(acc[t][j][2], acc[t][j][3]);
            }
        }

    // fused attention dots over this block's 64 columns (fp32 accs)
#pragma unroll
    for (int t = 0; t < 2; t++) {
        float s0 = 0.f, d0 = 0.f, s1 = 0.f, d1 = 0.f;
#pragma unroll
        for (int j = 0; j < 4; j++) {
            int cg = colBase + n_warp + j * 8 + 2 * c;
            float w0 = __ldg(att_s + cg), w1 = __ldg(att_s + cg + 1);
            float v0 = __ldg(att_d + cg), v1 = __ldg(att_d + cg + 1);
            s0 += acc[t][j][0] * w0 + acc[t][j][1] * w1;
            d0 += acc[t][j][0] * v0 + acc[t][j][1] * v1;
            s1 += acc[t][j][2] * w0 + acc[t][j][3] * w1;
            d1 += acc[t][j][2] * v0 + acc[t][j][3] * v1;
        }
#pragma unroll
        for (int o = 1; o < 4; o <<= 1) {
            s0 += __shfl_xor_sync(0xffffffffu, s0, o);
            d0 += __shfl_xor_sync(0xffffffffu, d0, o);
            s1 += __shfl_xor_sync(0xffffffffu, s1, o);
            d1 += __shfl_xor_sync(0xffffffffu, d1, o);
        }
        if (c == 0) {
            int rl = m_warp + t * 16 + g;
            atomicAdd(&sAs[rl], s0);     atomicAdd(&sAd[rl], d0);
            atomicAdd(&sAs[rl + 8], s1); atomicAdd(&sAd[rl + 8], d1);
        }
    }
    __syncthreads();
    if (tid < 128) {
        int gm = rowBase + tid;
        if (gm < M) {
            if (MODE == 0) {
                g_as1[gm * NH + blockIdx.x] = sAs[tid];
                g_ad1[gm * NH + blockIdx.x] = sAd[tid];
            } else {
                g_as2[gm] = sAs[tid];
                g_ad2[gm] = sAd[tid];
            }
        }
    }
}

// ---------------- conv1: per-node softmax + aggregation (warp per node) ------
// Each lane owns 8 consecutive columns (lane*8 .. lane*8+7), head = lane>>3.
__global__ __launch_bounds__(256) void agg1_k(const float* __restrict__ b1) {
    int g = blockIdx.x * blockDim.x + threadIdx.x;
    int node = g >> 5, lane = g & 31;
    if (node >= NN) return;
    int beg = g_off[node], end = g_off[node + 1];

    float4 ad = *(const float4*)(g_ad1 + node * 4);
    float d0 = 0.f, d1 = 0.f, d2 = 0.f, d3 = 0.f;
    for (int k = beg + lane; k < end; k += 32) {
        int j = g_srcidx[k];
        float4 as = *(const float4*)(g_as1 + j * 4);
        float e0 = __expf(lrelu(as.x + ad.x));
        float e1 = __expf(lrelu(as.y + ad.y));
        float e2 = __expf(lrelu(as.z + ad.z));
        float e3 = __expf(lrelu(as.w + ad.w));
        *(float4*)(g_e1 + (size_t)k * 4) = make_float4(e0, e1, e2, e3);
        d0 += e0; d1 += e1; d2 += e2; d3 += e3;
    }
#pragma unroll
    for (int o = 16; o; o >>= 1) {
        d0 += __shfl_xor_sync(0xffffffffu, d0, o);
        d1 += __shfl_xor_sync(0xffffffffu, d1, o);
        d2 += __shfl_xor_sync(0xffffffffu, d2, o);
        d3 += __shfl_xor_sync(0xffffffffu, d3, o);
    }
    float i0 = 1.f / (d0 + 1e-16f), i1 = 1.f / (d1 + 1e-16f);
    float i2 = 1.f / (d2 + 1e-16f), i3 = 1.f / (d3 + 1e-16f);

    const bool s8 = (lane & 8) != 0, s16 = (lane & 16) != 0;
    float av[8] = {};
    int col = lane * 8;

    int k = beg;
    for (; k + 2 <= end; k += 2) {
        int j0 = g_srcidx[k], j1 = g_srcidx[k + 1];
        float4 e0v = *(const float4*)(g_e1 + (size_t)k * 4);
        float4 e1v = *(const float4*)(g_e1 + (size_t)(k + 1) * 4);
        float w0 = s16 ? (s8 ? e0v.w * i3 : e0v.z * i2) : (s8 ? e0v.y * i1 : e0v.x * i0);
        float w1 = s16 ? (s8 ? e1v.w * i3 : e1v.z * i2) : (s8 ? e1v.y * i1 : e1v.x * i0);
        float4 p0 = *(const float4*)(g_h1h + (size_t)j0 * F1 + col);
        float4 p1 = *(const float4*)(g_h1h + (size_t)j1 * F1 + col);
        const __half2* h0 = (const __half2*)&p0;
        const __half2* h1 = (const __half2*)&p1;
#pragma unroll
        for (int i = 0; i < 4; i++) {
            float2 f0 = __half22float2(h0[i]);
            float2 f1 = __half22float2(h1[i]);
            av[2 * i + 0] += w0 * f0.x + w1 * f1.x;
            av[2 * i + 1] += w0 * f0.y + w1 * f1.y;
        }
    }
    if (k < end) {
        int j0 = g_srcidx[k];
        float4 e0v = *(const float4*)(g_e1 + (size_t)k * 4);
        float w0 = s16 ? (s8 ? e0v.w * i3 : e0v.z * i2) : (s8 ? e0v.y * i1 : e0v.x * i0);
        float4 p0 = *(const float4*)(g_h1h + (size_t)j0 * F1 + col);
        const __half2* h0 = (const __half2*)&p0;
#pragma unroll
        for (int i = 0; i < 4; i++) {
            float2 f0 = __half22float2(h0[i]);
            av[2 * i + 0] += w0 * f0.x;
            av[2 * i + 1] += w0 * f0.y;
        }
    }

    float* op = g_out1 + (size_t)node * F1 + col;
    float4 bA = *(const float4*)(b1 + col);
    float4 bB = *(const float4*)(b1 + col + 4);
    float4 oA = make_float4(fmaxf(av[0] + bA.x, 0.f), fmaxf(av[1] + bA.y, 0.f),
                            fmaxf(av[2] + bA.z, 0.f), fmaxf(av[3] + bA.w, 0.f));
    float4 oB = make_float4(fmaxf(av[4] + bB.x, 0.f), fmaxf(av[5] + bB.y, 0.f),
                            fmaxf(av[6] + bB.z, 0.f), fmaxf(av[7] + bB.w, 0.f));
    *(float4*)op = oA;
    *(float4*)(op + 4) = oB;
}

// ---------------- conv2: per-node softmax + aggregation (warp per node) ------
__global__ __launch_bounds__(256) void agg2_k(const float* __restrict__ b2) {
    int g = blockIdx.x * blockDim.x + threadIdx.x;
    int node = g >> 5, lane = g & 31;
    if (node >= NN) return;
    int beg = g_off[node], end = g_off[node + 1];

    float ad = g_ad2[node];
    float den = 0.f;
    for (int k = beg + lane; k < end; k += 32) {
        int j = g_srcidx[k];
        float e = __expf(lrelu(g_as2[j] + ad));
        g_e2[k] = e;
        den += e;
    }
#pragma unroll
    for (int o = 16; o; o >>= 1) den += __shfl_xor_sync(0xffffffffu, den, o);
    float inv = 1.f / (den + 1e-16f);

    float a0 = 0.f, a1 = 0.f;
    int c = lane * 2;
    int k = beg;
    for (; k + 2 <= end; k += 2) {
        int j0 = g_srcidx[k], j1 = g_srcidx[k + 1];
        float w0 = g_e2[k] * inv, w1 = g_e2[k + 1] * inv;
        float2 v0 = *(const float2*)(g_h2 + (size_t)j0 * OUTC + c);
        float2 v1 = *(const float2*)(g_h2 + (size_t)j1 * OUTC + c);
        a0 += w0 * v0.x + w1 * v1.x;
        a1 += w0 * v0.y + w1 * v1.y;
    }
    if (k < end) {
        int j0 = g_srcidx[k];
        float w0 = g_e2[k] * inv;
        float2 v0 = *(const float2*)(g_h2 + (size_t)j0 * OUTC + c);
        a0 += w0 * v0.x; a1 += w0 * v0.y;
    }
    float2 bb = *(const float2*)(b2 + c);
    *(__half2*)(g_out2h + (size_t)node * OUTC + c) = __floats2half2_rn(a0 + bb.x, a1 + bb.y);
}

// ---------------- decode: logits (8 lanes per edge, 4 edges per warp) --------
__global__ void decode_k(const int* __restrict__ pos, const int* __restrict__ neg,
                         float* __restrict__ out) {
    int g = blockIdx.x * blockDim.x + threadIdx.x;
    int e = g >> 3, lane = g & 7;
    if (e >= 2 * EE) return;
    int a, b;
    if (e < EE) { a = pos[e]; b = pos[EE + e]; }
    else        { int t = e - EE; a = neg[t]; b = neg[EE + t]; }
    int c = lane * 8;
    float4 pa = *(const float4*)(g_out2h + (size_t)a * OUTC + c);
    float4 pb = *(const float4*)(g_out2h + (size_t)b * OUTC + c);
    const __half2* ha = (const __half2*)&pa;
    const __half2* hb = (const __half2*)&pb;
    float acc = 0.f;
#pragma unroll
    for (int i = 0; i < 4; i++) {
        float2 fa = __half22float2(ha[i]);
        float2 fb = __half22float2(hb[i]);
        acc += fa.x * fb.x + fa.y * fb.y;
    }
#pragma unroll
    for (int o = 4; o; o >>= 1) acc += __shfl_xor_sync(0xffffffffu, acc, o);
    if (!lane) out[e] = acc;
}

// ---------------- launch ----------------
extern "C" void kernel_launch(void* const* d_in, const int* in_sizes, int n_in,
                              void* d_out, int out_size) {
    const float* x    = (const float*)d_in[0];
    const int*   pos  = (const int*)d_in[1];
    const int*   neg  = (const int*)d_in[2];
    const float* W1   = (const float*)d_in[3];
    const float* as1v = (const float*)d_in[4];
    const float* ad1v = (const float*)d_in[5];
    const float* b1   = (const float*)d_in[6];
    const float* W2   = (const float*)d_in[7];
    const float* as2v = (const float*)d_in[8];
    const float* ad2v = (const float*)d_in[9];
    const float* b2   = (const float*)d_in[10];
    float* out = (float*)d_out;
    (void)in_sizes; (void)n_in; (void)out_size;

    static cudaStream_t s1 = nullptr;
    static cudaEvent_t evFork = nullptr, evJoin = nullptr;
    if (s1 == nullptr) {
        cudaStreamCreateWithFlags(&s1, cudaStreamNonBlocking);
        cudaEventCreateWithFlags(&evFork, cudaEventDisableTiming);
        cudaEventCreateWithFlags(&evJoin, cudaEventDisableTiming);
    }

    // fork: CSR build on s1, concurrent with gemm1 on the main stream
    cudaEventRecord(evFork, 0);
    cudaStreamWaitEvent(s1, evFork, 0);
    init_off_k<<<(NN + 256) / 256, 256, 0, s1>>>();
    hist_k<<<(EE + 255) / 256, 256, 0, s1>>>(pos);
    scan_k<<<1, 1024, 0, s1>>>();
    scatter_k<<<(ET + 255) / 256, 256, 0, s1>>>(pos);
    cudaEventRecord(evJoin, s1);

    // conv1 linear + fused attention dots
    mma_gemm_k<0><<<dim3(F1 / 64, (NN + 127) / 128), 256>>>(x, W1, as1v, ad1v, NN, F1, INC);

    cudaStreamWaitEvent(0, evJoin, 0);
    agg1_k<<<(NN * 32 + 255) / 256, 256>>>(b1);

    // conv2
    mma_gemm_k<1><<<dim3(OUTC / 64, (NN + 127) / 128), 256>>>(nullptr, W2, as2v, ad2v, NN, OUTC, F1);
    agg2_k<<<(NN * 32 + 255) / 256, 256>>>(b2);

    // decode
    decode_k<<<(2 * EE * 8 + 255) / 256, 256>>>(pos, neg, out);
}

// round 8
// speedup vs baseline: 2.2079x; 1.0458x over previous
#include <cuda_runtime.h>
#include <cuda_fp16.h>
#include <math.h>
#include <stdint.h>

#define NN    50000
#define EE    800000
#define INC   128
#define HIDC  64
#define NH    4
#define OUTC  64
#define F1    (NH * HIDC)        // 256
#define ET    (EE + NN)          // edges + self loops = 850000

// ---------------- scratch (device globals; no allocation) ----------------
__device__ __half g_h1h  [(size_t)NN * F1];   // x @ W1   (fp16 storage)
__device__ __half g_out1h[(size_t)NN * F1];   // z        (fp16 storage)
__device__ float  g_as1 [NN * NH];
__device__ float  g_ad1 [NN * NH];
__device__ float  g_e1  [(size_t)ET * NH];    // exp(alpha) per CSR slot
__device__ __half g_h2h [(size_t)NN * OUTC];  // z @ W2   (fp16 storage)
__device__ __half g_out2h[(size_t)NN * OUTC]; // z2       (fp16 storage)
__device__ float  g_as2 [NN];
__device__ float  g_ad2 [NN];
__device__ float  g_e2  [ET];
// CSR by destination (shared by both conv layers)
__device__ int    g_off [NN + 1];
__device__ int    g_fill[NN];
__device__ int    g_srcidx[ET];

__device__ __forceinline__ float lrelu(float v) { return v > 0.f ? v : 0.2f * v; }

// ---------------- CSR build ----------------
__global__ void init_off_k() {
    int i = blockIdx.x * blockDim.x + threadIdx.x;
    if (i <= NN) g_off[i] = (i == 0) ? 0 : 1;   // each node has 1 self loop
}

__global__ void hist_k(const int* __restrict__ ei) {
    int e = blockIdx.x * blockDim.x + threadIdx.x;
    if (e >= EE) return;
    atomicAdd(&g_off[ei[EE + e] + 1], 1);
}

// single-block 3-phase inclusive scan over g_off[0..NN]
__global__ void scan_k() {
    const int L = NN + 1;
    const int CH = (L + 1023) / 1024;
    __shared__ int wsum[32];
    int t = threadIdx.x, lane = t & 31, wid = t >> 5;
    int beg = t * CH;
    int end = beg + CH; if (end > L) end = L;

    int s = 0;
    for (int i = beg; i < end; i++) s += g_off[i];

    int incl = s;
#pragma unroll
    for (int o = 1; o < 32; o <<= 1) {
        int v = __shfl_up_sync(0xffffffffu, incl, o);
        if (lane >= o) incl += v;
    }
    if (lane == 31) wsum[wid] = incl;
    __syncthreads();
    if (wid == 0) {
        int w = wsum[lane];
        int wi = w;
#pragma unroll
        for (int o = 1; o < 32; o <<= 1) {
            int v = __shfl_up_sync(0xffffffffu, wi, o);
            if (lane >= o) wi += v;
        }
        wsum[lane] = wi - w;
    }
    __syncthreads();

    int run = (incl - s) + wsum[wid];
    for (int i = beg; i < end; i++) {
        run += g_off[i];
        g_off[i] = run;
        if (i < NN) g_fill[i] = run;
    }
}

__global__ void scatter_k(const int* __restrict__ ei) {
    int e = blockIdx.x * blockDim.x + threadIdx.x;
    if (e >= ET) return;
    int s, d;
    if (e < EE) { s = ei[e]; d = ei[EE + e]; } else { s = d = e - EE; }
    int p = atomicAdd(&g_fill[d], 1);
    g_srcidx[p] = s;
}

// ---------------- TF32 tensor-core GEMM (3xTF32 split) + fused attention ----
__device__ __forceinline__ void split_tf32(float x, uint32_t& hi, uint32_t& lo) {
    uint32_t h;
    asm("cvt.rna.tf32.f32 %0, %1;" : "=r"(h) : "f"(x));
    float l = x - __uint_as_float(h);
    asm("cvt.rna.tf32.f32 %0, %1;" : "=r"(lo) : "f"(l));
    hi = h;
}
__device__ __forceinline__ void mma_tf32(float* d, const uint32_t* a, const uint32_t* b) {
    asm volatile(
        "mma.sync.aligned.m16n8k8.row.col.f32.tf32.tf32.f32 "
        "{%0,%1,%2,%3}, {%4,%5,%6,%7}, {%8,%9}, {%0,%1,%2,%3};\n"
        : "+f"(d[0]), "+f"(d[1]), "+f"(d[2]), "+f"(d[3])
        : "r"(a[0]), "r"(a[1]), "r"(a[2]), "r"(a[3]), "r"(b[0]), "r"(b[1]));
}

// MODE 0: A = x (fp32 ext), C = g_h1h,  attn -> g_as1/g_ad1 per head (blockIdx.x)
// MODE 1: A = g_out1h (fp16), C = g_h2h, attn -> g_as2/g_ad2
template <int MODE>
__global__ __launch_bounds__(256) void mma_gemm_k(const float* __restrict__ Aext,
                                                  const float* __restrict__ B,
                                                  const float* __restrict__ att_s,
                                                  const float* __restrict__ att_d,
                                                  int M, int N, int K) {
    __shared__ __align__(16) float As[128 * 36];   // [row][k], stride 36
    __shared__ __align__(16) float Bs[32 * 72];    // [k][n],  stride 72
    __shared__ float sAs[128], sAd[128];

    int tid = threadIdx.x;
    int wid = tid >> 5, lane = tid & 31;
    int warp_m = wid >> 1, warp_n = wid & 1;
    int m_warp = warp_m * 32, n_warp = warp_n * 32;
    int g = lane >> 2, c = lane & 3;
    int rowBase = blockIdx.y * 128, colBase = blockIdx.x * 64;

    if (tid < 128) { sAs[tid] = 0.f; sAd[tid] = 0.f; }

    float acc[2][4][4] = {};

    for (int k0 = 0; k0 < K; k0 += 32) {
        if (MODE == 0) {
#pragma unroll
            for (int i = 0; i < 4; i++) {
                int fid = tid + i * 256;
                int row = fid >> 3, kq = (fid & 7) * 4;
                int gm = rowBase + row;
                float4 v = make_float4(0.f, 0.f, 0.f, 0.f);
                if (gm < M) v = *(const float4*)(Aext + (size_t)gm * K + k0 + kq);
                *(float4*)&As[row * 36 + kq] = v;
            }
        } else {
#pragma unroll
            for (int i = 0; i < 2; i++) {
                int fid = tid + i * 256;               // 512 loads of 8 halves
                int row = fid >> 2, kq = (fid & 3) * 8;
                int gm = rowBase + row;
                float f[8];
                if (gm < M) {
                    float4 p = *(const float4*)(g_out1h + (size_t)gm * K + k0 + kq);
                    const __half2* hp = (const __half2*)&p;
#pragma unroll
                    for (int q = 0; q < 4; q++) {
                        float2 fv = __half22float2(hp[q]);
                        f[2 * q] = fv.x; f[2 * q + 1] = fv.y;
                    }
                } else {
#pragma unroll
                    for (int q = 0; q < 8; q++) f[q] = 0.f;
                }
#pragma unroll
                for (int q = 0; q < 8; q++) As[row * 36 + kq + q] = f[q];
            }
        }
#pragma unroll
        for (int i = 0; i < 2; i++) {
            int fid = tid + i * 256;
            int kr = fid >> 4, nq = (fid & 15) * 4;
            float4 v = *(const float4*)(B + (size_t)(k0 + kr) * N + colBase + nq);
            *(float4*)&Bs[kr * 72 + nq] = v;
        }
        __syncthreads();

#pragma unroll
        for (int ks = 0; ks < 32; ks += 8) {
            uint32_t ah[2][4], al[2][4], bh[4][2], bl[4][2];
#pragma unroll
            for (int t = 0; t < 2; t++) {
                int r0 = (m_warp + t * 16 + g) * 36 + ks + c;
                int r1 = r0 + 8 * 36;
                split_tf32(As[r0],     ah[t][0], al[t][0]);
                split_tf32(As[r1],     ah[t][1], al[t][1]);
                split_tf32(As[r0 + 4], ah[t][2], al[t][2]);
                split_tf32(As[r1 + 4], ah[t][3], al[t][3]);
            }
#pragma unroll
            for (int j = 0; j < 4; j++) {
                int col = n_warp + j * 8 + g;
                split_tf32(Bs[(ks + c) * 72 + col],     bh[j][0], bl[j][0]);
                split_tf32(Bs[(ks + c + 4) * 72 + col], bh[j][1], bl[j][1]);
            }
#pragma unroll
            for (int t = 0; t < 2; t++)
#pragma unroll
                for (int j = 0; j < 4; j++) {
                    mma_tf32(acc[t][j], ah[t], bh[j]);
                    mma_tf32(acc[t][j], ah[t], bl[j]);
                    mma_tf32(acc[t][j], al[t], bh[j]);
                }
        }
        __syncthreads();
    }

    // write C as fp16
    __half* Ch = (MODE == 0) ? g_h1h : g_h2h;
#pragma unroll
    for (int t = 0; t < 2; t++)
#pragma unroll
        for (int j = 0; j < 4; j++) {
            int r0 = rowBase + m_warp + t * 16 + g;
            int r1 = r0 + 8;
            int cc = colBase + n_warp + j * 8 + 2 * c;
            if (r0 < M)
                *(__half2*)&Ch[(size_t)r0 * N + cc] = __floats2half2_rn(acc[t][j][0], acc[t][j][1]);
            if (r1 < M)
                *(__half2*)&Ch[(size_t)r1 * N + cc] = __floats2half2_rn(acc[t][j][2], acc[t][j][3]);
        }

    // fused attention dots over this block's 64 columns (fp32 accs)
#pragma unroll
    for (int t = 0; t < 2; t++) {
        float s0 = 0.f, d0 = 0.f, s1 = 0.f, d1 = 0.f;
#pragma unroll
        for (int j = 0; j < 4; j++) {
            int cg = colBase + n_warp + j * 8 + 2 * c;
            float w0 = __ldg(att_s + cg), w1 = __ldg(att_s + cg + 1);
            float v0 = __ldg(att_d + cg), v1 = __ldg(att_d + cg + 1);
            s0 += acc[t][j][0] * w0 + acc[t][j][1] * w1;
            d0 += acc[t][j][0] * v0 + acc[t][j][1] * v1;
            s1 += acc[t][j][2] * w0 + acc[t][j][3] * w1;
            d1 += acc[t][j][2] * v0 + acc[t][j][3] * v1;
        }
#pragma unroll
        for (int o = 1; o < 4; o <<= 1) {
            s0 += __shfl_xor_sync(0xffffffffu, s0, o);
            d0 += __shfl_xor_sync(0xffffffffu, d0, o);
            s1 += __shfl_xor_sync(0xffffffffu, s1, o);
            d1 += __shfl_xor_sync(0xffffffffu, d1, o);
        }
        if (c == 0) {
            int rl = m_warp + t * 16 + g;
            atomicAdd(&sAs[rl], s0);     atomicAdd(&sAd[rl], d0);
            atomicAdd(&sAs[rl + 8], s1); atomicAdd(&sAd[rl + 8], d1);
        }
    }
    __syncthreads();
    if (tid < 128) {
        int gm = rowBase + tid;
        if (gm < M) {
            if (MODE == 0) {
                g_as1[gm * NH + blockIdx.x] = sAs[tid];
                g_ad1[gm * NH + blockIdx.x] = sAd[tid];
            } else {
                g_as2[gm] = sAs[tid];
                g_ad2[gm] = sAd[tid];
            }
        }
    }
}

// ---------------- conv1: per-node softmax + aggregation (warp per node) ------
// Each lane owns 8 consecutive columns (lane*8 .. lane*8+7), head = lane>>3.
__global__ __launch_bounds__(256) void agg1_k(const float* __restrict__ b1) {
    int g = blockIdx.x * blockDim.x + threadIdx.x;
    int node = g >> 5, lane = g & 31;
    if (node >= NN) return;
    int beg = g_off[node], end = g_off[node + 1];

    float4 ad = *(const float4*)(g_ad1 + node * 4);
    float d0 = 0.f, d1 = 0.f, d2 = 0.f, d3 = 0.f;
    for (int k = beg + lane; k < end; k += 32) {
        int j = g_srcidx[k];
        float4 as = *(const float4*)(g_as1 + j * 4);
        float e0 = __expf(lrelu(as.x + ad.x));
        float e1 = __expf(lrelu(as.y + ad.y));
        float e2 = __expf(lrelu(as.z + ad.z));
        float e3 = __expf(lrelu(as.w + ad.w));
        *(float4*)(g_e1 + (size_t)k * 4) = make_float4(e0, e1, e2, e3);
        d0 += e0; d1 += e1; d2 += e2; d3 += e3;
    }
#pragma unroll
    for (int o = 16; o; o >>= 1) {
        d0 += __shfl_xor_sync(0xffffffffu, d0, o);
        d1 += __shfl_xor_sync(0xffffffffu, d1, o);
        d2 += __shfl_xor_sync(0xffffffffu, d2, o);
        d3 += __shfl_xor_sync(0xffffffffu, d3, o);
    }
    float i0 = 1.f / (d0 + 1e-16f), i1 = 1.f / (d1 + 1e-16f);
    float i2 = 1.f / (d2 + 1e-16f), i3 = 1.f / (d3 + 1e-16f);

    const bool s8 = (lane & 8) != 0, s16 = (lane & 16) != 0;
    float av[8] = {};
    int col = lane * 8;

    int k = beg;
    for (; k + 4 <= end; k += 4) {
        int j0 = g_srcidx[k],     j1 = g_srcidx[k + 1];
        int j2 = g_srcidx[k + 2], j3 = g_srcidx[k + 3];
        float4 e0v = *(const float4*)(g_e1 + (size_t)k * 4);
        float4 e1v = *(const float4*)(g_e1 + (size_t)(k + 1) * 4);
        float4 e2v = *(const float4*)(g_e1 + (size_t)(k + 2) * 4);
        float4 e3v = *(const float4*)(g_e1 + (size_t)(k + 3) * 4);
        float w0 = s16 ? (s8 ? e0v.w * i3 : e0v.z * i2) : (s8 ? e0v.y * i1 : e0v.x * i0);
        float w1 = s16 ? (s8 ? e1v.w * i3 : e1v.z * i2) : (s8 ? e1v.y * i1 : e1v.x * i0);
        float w2 = s16 ? (s8 ? e2v.w * i3 : e2v.z * i2) : (s8 ? e2v.y * i1 : e2v.x * i0);
        float w3 = s16 ? (s8 ? e3v.w * i3 : e3v.z * i2) : (s8 ? e3v.y * i1 : e3v.x * i0);
        float4 p0 = *(const float4*)(g_h1h + (size_t)j0 * F1 + col);
        float4 p1 = *(const float4*)(g_h1h + (size_t)j1 * F1 + col);
        float4 p2 = *(const float4*)(g_h1h + (size_t)j2 * F1 + col);
        float4 p3 = *(const float4*)(g_h1h + (size_t)j3 * F1 + col);
        const __half2* h0 = (const __half2*)&p0;
        const __half2* h1 = (const __half2*)&p1;
        const __half2* h2 = (const __half2*)&p2;
        const __half2* h3 = (const __half2*)&p3;
#pragma unroll
        for (int i = 0; i < 4; i++) {
            float2 f0 = __half22float2(h0[i]);
            float2 f1 = __half22float2(h1[i]);
            float2 f2 = __half22float2(h2[i]);
            float2 f3 = __half22float2(h3[i]);
            av[2 * i + 0] += w0 * f0.x + w1 * f1.x + w2 * f2.x + w3 * f3.x;
            av[2 * i + 1] += w0 * f0.y + w1 * f1.y + w2 * f2.y + w3 * f3.y;
        }
    }
    for (; k < end; k++) {
        int j0 = g_srcidx[k];
        float4 e0v = *(const float4*)(g_e1 + (size_t)k * 4);
        float w0 = s16 ? (s8 ? e0v.w * i3 : e0v.z * i2) : (s8 ? e0v.y * i1 : e0v.x * i0);
        float4 p0 = *(const float4*)(g_h1h + (size_t)j0 * F1 + col);
        const __half2* h0 = (const __half2*)&p0;
#pragma unroll
        for (int i = 0; i < 4; i++) {
            float2 f0 = __half22float2(h0[i]);
            av[2 * i + 0] += w0 * f0.x;
            av[2 * i + 1] += w0 * f0.y;
        }
    }

    float4 bA = *(const float4*)(b1 + col);
    float4 bB = *(const float4*)(b1 + col + 4);
    __half2 o01 = __floats2half2_rn(fmaxf(av[0] + bA.x, 0.f), fmaxf(av[1] + bA.y, 0.f));
    __half2 o23 = __floats2half2_rn(fmaxf(av[2] + bA.z, 0.f), fmaxf(av[3] + bA.w, 0.f));
    __half2 o45 = __floats2half2_rn(fmaxf(av[4] + bB.x, 0.f), fmaxf(av[5] + bB.y, 0.f));
    __half2 o67 = __floats2half2_rn(fmaxf(av[6] + bB.z, 0.f), fmaxf(av[7] + bB.w, 0.f));
    __half2 pack[4] = {o01, o23, o45, o67};
    *(float4*)(g_out1h + (size_t)node * F1 + col) = *(const float4*)pack;
}

// ---------------- conv2: per-node softmax + aggregation (warp per node) ------
__global__ __launch_bounds__(256) void agg2_k(const float* __restrict__ b2) {
    int g = blockIdx.x * blockDim.x + threadIdx.x;
    int node = g >> 5, lane = g & 31;
    if (node >= NN) return;
    int beg = g_off[node], end = g_off[node + 1];

    float ad = g_ad2[node];
    float den = 0.f;
    for (int k = beg + lane; k < end; k += 32) {
        int j = g_srcidx[k];
        float e = __expf(lrelu(g_as2[j] + ad));
        g_e2[k] = e;
        den += e;
    }
#pragma unroll
    for (int o = 16; o; o >>= 1) den += __shfl_xor_sync(0xffffffffu, den, o);
    float inv = 1.f / (den + 1e-16f);

    float a0 = 0.f, a1 = 0.f;
    int c = lane * 2;
    int k = beg;
    for (; k + 4 <= end; k += 4) {
        int j0 = g_srcidx[k],     j1 = g_srcidx[k + 1];
        int j2 = g_srcidx[k + 2], j3 = g_srcidx[k + 3];
        float w0 = g_e2[k] * inv,     w1 = g_e2[k + 1] * inv;
        float w2 = g_e2[k + 2] * inv, w3 = g_e2[k + 3] * inv;
        float2 v0 = __half22float2(*(const __half2*)(g_h2h + (size_t)j0 * OUTC + c));
        float2 v1 = __half22float2(*(const __half2*)(g_h2h + (size_t)j1 * OUTC + c));
        float2 v2 = __half22float2(*(const __half2*)(g_h2h + (size_t)j2 * OUTC + c));
        float2 v3 = __half22float2(*(const __half2*)(g_h2h + (size_t)j3 * OUTC + c));
        a0 += w0 * v0.x + w1 * v1.x + w2 * v2.x + w3 * v3.x;
        a1 += w0 * v0.y + w1 * v1.y + w2 * v2.y + w3 * v3.y;
    }
    for (; k < end; k++) {
        int j0 = g_srcidx[k];
        float w0 = g_e2[k] * inv;
        float2 v0 = __half22float2(*(const __half2*)(g_h2h + (size_t)j0 * OUTC + c));
        a0 += w0 * v0.x; a1 += w0 * v0.y;
    }
    float2 bb = *(const float2*)(b2 + c);
    *(__half2*)(g_out2h + (size_t)node * OUTC + c) = __floats2half2_rn(a0 + bb.x, a1 + bb.y);
}

// ---------------- decode: logits (8 lanes per edge, 4 edges per warp) --------
__global__ void decode_k(const int* __restrict__ pos, const int* __restrict__ neg,
                         float* __restrict__ out) {
    int g = blockIdx.x * blockDim.x + threadIdx.x;
    int e = g >> 3, lane = g & 7;
    if (e >= 2 * EE) return;
    int a, b;
    if (e < EE) { a = pos[e]; b = pos[EE + e]; }
    else        { int t = e - EE; a = neg[t]; b = neg[EE + t]; }
    int c = lane * 8;
    float4 pa = *(const float4*)(g_out2h + (size_t)a * OUTC + c);
    float4 pb = *(const float4*)(g_out2h + (size_t)b * OUTC + c);
    const __half2* ha = (const __half2*)&pa;
    const __half2* hb = (const __half2*)&pb;
    float acc = 0.f;
#pragma unroll
    for (int i = 0; i < 4; i++) {
        float2 fa = __half22float2(ha[i]);
        float2 fb = __half22float2(hb[i]);
        acc += fa.x * fb.x + fa.y * fb.y;
    }
#pragma unroll
    for (int o = 4; o; o >>= 1) acc += __shfl_xor_sync(0xffffffffu, acc, o);
    if (!lane) out[e] = acc;
}

// ---------------- launch ----------------
extern "C" void kernel_launch(void* const* d_in, const int* in_sizes, int n_in,
                              void* d_out, int out_size) {
    const float* x    = (const float*)d_in[0];
    const int*   pos  = (const int*)d_in[1];
    const int*   neg  = (const int*)d_in[2];
    const float* W1   = (const float*)d_in[3];
    const float* as1v = (const float*)d_in[4];
    const float* ad1v = (const float*)d_in[5];
    const float* b1   = (const float*)d_in[6];
    const float* W2   = (const float*)d_in[7];
    const float* as2v = (const float*)d_in[8];
    const float* ad2v = (const float*)d_in[9];
    const float* b2   = (const float*)d_in[10];
    float* out = (float*)d_out;
    (void)in_sizes; (void)n_in; (void)out_size;

    static cudaStream_t s1 = nullptr;
    static cudaEvent_t evFork = nullptr, evJoin = nullptr;
    if (s1 == nullptr) {
        cudaStreamCreateWithFlags(&s1, cudaStreamNonBlocking);
        cudaEventCreateWithFlags(&evFork, cudaEventDisableTiming);
        cudaEventCreateWithFlags(&evJoin, cudaEventDisableTiming);
    }

    // fork: CSR build on s1, concurrent with gemm1 on the main stream
    cudaEventRecord(evFork, 0);
    cudaStreamWaitEvent(s1, evFork, 0);
    init_off_k<<<(NN + 256) / 256, 256, 0, s1>>>();
    hist_k<<<(EE + 255) / 256, 256, 0, s1>>>(pos);
    scan_k<<<1, 1024, 0, s1>>>();
    scatter_k<<<(ET + 255) / 256, 256, 0, s1>>>(pos);
    cudaEventRecord(evJoin, s1);

    // conv1 linear + fused attention dots
    mma_gemm_k<0><<<dim3(F1 / 64, (NN + 127) / 128), 256>>>(x, W1, as1v, ad1v, NN, F1, INC);

    cudaStreamWaitEvent(0, evJoin, 0);
    agg1_k<<<(NN * 32 + 255) / 256, 256>>>(b1);

    // conv2
    mma_gemm_k<1><<<dim3(OUTC / 64, (NN + 127) / 128), 256>>>(nullptr, W2, as2v, ad2v, NN, OUTC, F1);
    agg2_k<<<(NN * 32 + 255) / 256, 256>>>(b2);

    // decode
    decode_k<<<(2 * EE * 8 + 255) / 256, 256>>>(pos, neg, out);
}

// round 10
// speedup vs baseline: 2.2243x; 1.0074x over previous
#include <cuda_runtime.h>
#include <cuda_fp16.h>
#include <math.h>
#include <stdint.h>

#define NN    50000
#define EE    800000
#define INC   128
#define HIDC  64
#define NH    4
#define OUTC  64
#define F1    (NH * HIDC)        // 256
#define ET    (EE + NN)          // edges + self loops = 850000

// ---------------- scratch (device globals; no allocation) ----------------
__device__ __half g_h1h  [(size_t)NN * F1];   // x @ W1   (fp16 storage)
__device__ __half g_out1h[(size_t)NN * F1];   // z        (fp16 storage)
__device__ float  g_as1 [NN * NH];
__device__ float  g_ad1 [NN * NH];
__device__ __half g_h2h [(size_t)NN * OUTC];  // z @ W2   (fp16 storage)
__device__ __half g_out2h[(size_t)NN * OUTC]; // z2       (fp16 storage)
__device__ float  g_as2 [NN];
__device__ float  g_ad2 [NN];
// CSR by destination (shared by both conv layers)
__device__ int    g_off [NN + 1];
__device__ int    g_fill[NN];
__device__ int    g_srcidx[ET];

__device__ __forceinline__ float lrelu(float v) { return v > 0.f ? v : 0.2f * v; }

// ---------------- CSR build ----------------
__global__ void init_off_k() {
    int i = blockIdx.x * blockDim.x + threadIdx.x;
    if (i <= NN) g_off[i] = (i == 0) ? 0 : 1;   // each node has 1 self loop
}

__global__ void hist_k(const int* __restrict__ ei) {
    int e = blockIdx.x * blockDim.x + threadIdx.x;
    if (e >= EE) return;
    atomicAdd(&g_off[ei[EE + e] + 1], 1);
}

// single-block 3-phase inclusive scan over g_off[0..NN]
__global__ void scan_k() {
    const int L = NN + 1;
    const int CH = (L + 1023) / 1024;
    __shared__ int wsum[32];
    int t = threadIdx.x, lane = t & 31, wid = t >> 5;
    int beg = t * CH;
    int end = beg + CH; if (end > L) end = L;

    int s = 0;
    for (int i = beg; i < end; i++) s += g_off[i];

    int incl = s;
#pragma unroll
    for (int o = 1; o < 32; o <<= 1) {
        int v = __shfl_up_sync(0xffffffffu, incl, o);
        if (lane >= o) incl += v;
    }
    if (lane == 31) wsum[wid] = incl;
    __syncthreads();
    if (wid == 0) {
        int w = wsum[lane];
        int wi = w;
#pragma unroll
        for (int o = 1; o < 32; o <<= 1) {
            int v = __shfl_up_sync(0xffffffffu, wi, o);
            if (lane >= o) wi += v;
        }
        wsum[lane] = wi - w;
    }
    __syncthreads();

    int run = (incl - s) + wsum[wid];
    for (int i = beg; i < end; i++) {
        run += g_off[i];
        g_off[i] = run;
        if (i < NN) g_fill[i] = run;
    }
}

__global__ void scatter_k(const int* __restrict__ ei) {
    int e = blockIdx.x * blockDim.x + threadIdx.x;
    if (e >= ET) return;
    int s, d;
    if (e < EE) { s = ei[e]; d = ei[EE + e]; } else { s = d = e - EE; }
    int p = atomicAdd(&g_fill[d], 1);
    g_srcidx[p] = s;
}

// ---------------- TF32 tensor-core GEMM (3xTF32, pre-split staging) ---------
// BM=128, BN=64, BK=16; splits computed once at staging, inner loop = LDS+MMA.
__device__ __forceinline__ void split_tf32(float x, uint32_t& hi, uint32_t& lo) {
    uint32_t h;
    asm("cvt.rna.tf32.f32 %0, %1;" : "=r"(h) : "f"(x));
    float l = x - __uint_as_float(h);
    asm("cvt.rna.tf32.f32 %0, %1;" : "=r"(lo) : "f"(l));
    hi = h;
}
__device__ __forceinline__ void mma_tf32(float* d, const uint32_t* a, const uint32_t* b) {
    asm volatile(
        "mma.sync.aligned.m16n8k8.row.col.f32.tf32.tf32.f32 "
        "{%0,%1,%2,%3}, {%4,%5,%6,%7}, {%8,%9}, {%0,%1,%2,%3};\n"
        : "+f"(d[0]), "+f"(d[1]), "+f"(d[2]), "+f"(d[3])
        : "r"(a[0]), "r"(a[1]), "r"(a[2]), "r"(a[3]), "r"(b[0]), "r"(b[1]));
}

#define A_STRIDE 20   // words, conflict-free for (g*20 + c) mod 32
#define B_STRIDE 72   // words, conflict-free for (c*72 + col) mod 32

// MODE 0: A = x (fp32 ext), C = g_h1h,  attn -> g_as1/g_ad1 per head (blockIdx.x)
// MODE 1: A = g_out1h (fp16), C = g_h2h, attn -> g_as2/g_ad2
template <int MODE>
__global__ __launch_bounds__(256) void mma_gemm_k(const float* __restrict__ Aext,
                                                  const float* __restrict__ B,
                                                  const float* __restrict__ att_s,
                                                  const float* __restrict__ att_d,
                                                  int M, int N, int K) {
    __shared__ __align__(16) uint32_t Ash[128 * A_STRIDE];
    __shared__ __align__(16) uint32_t Asl[128 * A_STRIDE];
    __shared__ __align__(16) uint32_t Bsh[16 * B_STRIDE];
    __shared__ __align__(16) uint32_t Bsl[16 * B_STRIDE];
    __shared__ float sAs[128], sAd[128];

    int tid = threadIdx.x;
    int wid = tid >> 5, lane = tid & 31;
    int warp_m = wid >> 1, warp_n = wid & 1;
    int m_warp = warp_m * 32, n_warp = warp_n * 32;
    int g = lane >> 2, c = lane & 3;
    int rowBase = blockIdx.y * 128, colBase = blockIdx.x * 64;

    if (tid < 128) { sAs[tid] = 0.f; sAd[tid] = 0.f; }

    float acc[2][4][4] = {};

    for (int k0 = 0; k0 < K; k0 += 16) {
        // ---- stage A (pre-split) ----
        if (MODE == 0) {
#pragma unroll
            for (int i = 0; i < 2; i++) {
                int fid = tid + i * 256;
                int row = fid >> 2, kq = (fid & 3) * 4;
                int gm = rowBase + row;
                float4 v = make_float4(0.f, 0.f, 0.f, 0.f);
                if (gm < M) v = *(const float4*)(Aext + (size_t)gm * K + k0 + kq);
                uint32_t h[4], l[4];
                split_tf32(v.x, h[0], l[0]); split_tf32(v.y, h[1], l[1]);
                split_tf32(v.z, h[2], l[2]); split_tf32(v.w, h[3], l[3]);
                *(uint4*)&Ash[row * A_STRIDE + kq] = make_uint4(h[0], h[1], h[2], h[3]);
                *(uint4*)&Asl[row * A_STRIDE + kq] = make_uint4(l[0], l[1], l[2], l[3]);
            }
        } else {
            int row = tid >> 1, kq = (tid & 1) * 8;
            int gm = rowBase + row;
            float f[8];
            if (gm < M) {
                float4 p = *(const float4*)(g_out1h + (size_t)gm * K + k0 + kq);
                const __half2* hp = (const __half2*)&p;
#pragma unroll
                for (int q = 0; q < 4; q++) {
                    float2 fv = __half22float2(hp[q]);
                    f[2 * q] = fv.x; f[2 * q + 1] = fv.y;
                }
            } else {
#pragma unroll
                for (int q = 0; q < 8; q++) f[q] = 0.f;
            }
            uint32_t h[8], l[8];
#pragma unroll
            for (int q = 0; q < 8; q++) split_tf32(f[q], h[q], l[q]);
            *(uint4*)&Ash[row * A_STRIDE + kq]     = make_uint4(h[0], h[1], h[2], h[3]);
            *(uint4*)&Ash[row * A_STRIDE + kq + 4] = make_uint4(h[4], h[5], h[6], h[7]);
            *(uint4*)&Asl[row * A_STRIDE + kq]     = make_uint4(l[0], l[1], l[2], l[3]);
            *(uint4*)&Asl[row * A_STRIDE + kq + 4] = make_uint4(l[4], l[5], l[6], l[7]);
        }
        // ---- stage B (pre-split): 16 k x 64 n ----
        {
            int kr = tid >> 4, nq = (tid & 15) * 4;
            float4 v = *(const float4*)(B + (size_t)(k0 + kr) * N + colBase + nq);
            uint32_t h[4], l[4];
            split_tf32(v.x, h[0], l[0]); split_tf32(v.y, h[1], l[1]);
            split_tf32(v.z, h[2], l[2]); split_tf32(v.w, h[3], l[3]);
            *(uint4*)&Bsh[kr * B_STRIDE + nq] = make_uint4(h[0], h[1], h[2], h[3]);
            *(uint4*)&Bsl[kr * B_STRIDE + nq] = make_uint4(l[0], l[1], l[2], l[3]);
        }
        __syncthreads();

#pragma unroll
        for (int ks = 0; ks < 16; ks += 8) {
            uint32_t ah[2][4], al[2][4], bh[4][2], bl[4][2];
#pragma unroll
            for (int t = 0; t < 2; t++) {
                int r0 = (m_warp + t * 16 + g) * A_STRIDE + ks + c;
                int r1 = r0 + 8 * A_STRIDE;
                ah[t][0] = Ash[r0];     al[t][0] = Asl[r0];
                ah[t][1] = Ash[r1];     al[t][1] = Asl[r1];
                ah[t][2] = Ash[r0 + 4]; al[t][2] = Asl[r0 + 4];
                ah[t][3] = Ash[r1 + 4]; al[t][3] = Asl[r1 + 4];
            }
#pragma unroll
            for (int j = 0; j < 4; j++) {
                int col = n_warp + j * 8 + g;
                bh[j][0] = Bsh[(ks + c) * B_STRIDE + col];
                bl[j][0] = Bsl[(ks + c) * B_STRIDE + col];
                bh[j][1] = Bsh[(ks + c + 4) * B_STRIDE + col];
                bl[j][1] = Bsl[(ks + c + 4) * B_STRIDE + col];
            }
#pragma unroll
            for (int t = 0; t < 2; t++)
#pragma unroll
                for (int j = 0; j < 4; j++) {
                    mma_tf32(acc[t][j], ah[t], bh[j]);
                    mma_tf32(acc[t][j], ah[t], bl[j]);
                    mma_tf32(acc[t][j], al[t], bh[j]);
                }
        }
        __syncthreads();
    }

    // write C as fp16
    __half* Ch = (MODE == 0) ? g_h1h : g_h2h;
#pragma unroll
    for (int t = 0; t < 2; t++)
#pragma unroll
        for (int j = 0; j < 4; j++) {
            int r0 = rowBase + m_warp + t * 16 + g;
            int r1 = r0 + 8;
            int cc = colBase + n_warp + j * 8 + 2 * c;
            if (r0 < M)
                *(__half2*)&Ch[(size_t)r0 * N + cc] = __floats2half2_rn(acc[t][j][0], acc[t][j][1]);
            if (r1 < M)
                *(__half2*)&Ch[(size_t)r1 * N + cc] = __floats2half2_rn(acc[t][j][2], acc[t][j][3]);
        }

    // fused attention dots over this block's 64 columns
#pragma unroll
    for (int t = 0; t < 2; t++) {
        float s0 = 0.f, d0 = 0.f, s1 = 0.f, d1 = 0.f;
#pragma unroll
        for (int j = 0; j < 4; j++) {
            int cg = colBase + n_warp + j * 8 + 2 * c;
            float w0 = __ldg(att_s + cg), w1 = __ldg(att_s + cg + 1);
            float v0 = __ldg(att_d + cg), v1 = __ldg(att_d + cg + 1);
            s0 += acc[t][j][0] * w0 + acc[t][j][1] * w1;
            d0 += acc[t][j][0] * v0 + acc[t][j][1] * v1;
            s1 += acc[t][j][2] * w0 + acc[t][j][3] * w1;
            d1 += acc[t][j][2] * v0 + acc[t][j][3] * v1;
        }
#pragma unroll
        for (int o = 1; o < 4; o <<= 1) {
            s0 += __shfl_xor_sync(0xffffffffu, s0, o);
            d0 += __shfl_xor_sync(0xffffffffu, d0, o);
            s1 += __shfl_xor_sync(0xffffffffu, s1, o);
            d1 += __shfl_xor_sync(0xffffffffu, d1, o);
        }
        if (c == 0) {
            int rl = m_warp + t * 16 + g;
            atomicAdd(&sAs[rl], s0);     atomicAdd(&sAd[rl], d0);
            atomicAdd(&sAs[rl + 8], s1); atomicAdd(&sAd[rl + 8], d1);
        }
    }
    __syncthreads();
    if (tid < 128) {
        int gm = rowBase + tid;
        if (gm < M) {
            if (MODE == 0) {
                g_as1[gm * NH + blockIdx.x] = sAs[tid];
                g_ad1[gm * NH + blockIdx.x] = sAd[tid];
            } else {
                g_as2[gm] = sAs[tid];
                g_ad2[gm] = sAd[tid];
            }
        }
    }
}

// ---------------- conv1: fused softmax+aggregation (warp/node, smem-staged) --
#define CAP 64
__global__ __launch_bounds__(256) void agg1_k(const float* __restrict__ b1) {
    __shared__ int    sj[8][CAP];
    __shared__ float4 se[8][CAP];
    int wslot = threadIdx.x >> 5, lane = threadIdx.x & 31;
    int node = blockIdx.x * 8 + wslot;
    if (node >= NN) return;
    int beg = g_off[node], deg = g_off[node + 1] - beg;

    float4 ad = *(const float4*)(g_ad1 + node * 4);
    float d0 = 0.f, d1 = 0.f, d2 = 0.f, d3 = 0.f;
    for (int kk = lane; kk < deg; kk += 32) {
        int j = g_srcidx[beg + kk];
        float4 as = *(const float4*)(g_as1 + j * 4);
        float e0 = __expf(lrelu(as.x + ad.x));
        float e1 = __expf(lrelu(as.y + ad.y));
        float e2 = __expf(lrelu(as.z + ad.z));
        float e3 = __expf(lrelu(as.w + ad.w));
        d0 += e0; d1 += e1; d2 += e2; d3 += e3;
        if (kk < CAP) { sj[wslot][kk] = j; se[wslot][kk] = make_float4(e0, e1, e2, e3); }
    }
#pragma unroll
    for (int o = 16; o; o >>= 1) {
        d0 += __shfl_xor_sync(0xffffffffu, d0, o);
        d1 += __shfl_xor_sync(0xffffffffu, d1, o);
        d2 += __shfl_xor_sync(0xffffffffu, d2, o);
        d3 += __shfl_xor_sync(0xffffffffu, d3, o);
    }
    float i0 = 1.f / (d0 + 1e-16f), i1 = 1.f / (d1 + 1e-16f);
    float i2 = 1.f / (d2 + 1e-16f), i3 = 1.f / (d3 + 1e-16f);
    __syncwarp();

    const bool s8 = (lane & 8) != 0, s16 = (lane & 16) != 0;
    float av[8] = {};
    int col = lane * 8;
    int cap = deg < CAP ? deg : CAP;

    int kk = 0;
    for (; kk + 4 <= cap; kk += 4) {
        int j0 = sj[wslot][kk],     j1 = sj[wslot][kk + 1];
        int j2 = sj[wslot][kk + 2], j3 = sj[wslot][kk + 3];
        float4 e0v = se[wslot][kk],     e1v = se[wslot][kk + 1];
        float4 e2v = se[wslot][kk + 2], e3v = se[wslot][kk + 3];
        float w0 = s16 ? (s8 ? e0v.w * i3 : e0v.z * i2) : (s8 ? e0v.y * i1 : e0v.x * i0);
        float w1 = s16 ? (s8 ? e1v.w * i3 : e1v.z * i2) : (s8 ? e1v.y * i1 : e1v.x * i0);
        float w2 = s16 ? (s8 ? e2v.w * i3 : e2v.z * i2) : (s8 ? e2v.y * i1 : e2v.x * i0);
        float w3 = s16 ? (s8 ? e3v.w * i3 : e3v.z * i2) : (s8 ? e3v.y * i1 : e3v.x * i0);
        float4 p0 = *(const float4*)(g_h1h + (size_t)j0 * F1 + col);
        float4 p1 = *(const float4*)(g_h1h + (size_t)j1 * F1 + col);
        float4 p2 = *(const float4*)(g_h1h + (size_t)j2 * F1 + col);
        float4 p3 = *(const float4*)(g_h1h + (size_t)j3 * F1 + col);
        const __half2* h0 = (const __half2*)&p0;
        const __half2* h1 = (const __half2*)&p1;
        const __half2* h2 = (const __half2*)&p2;
        const __half2* h3 = (const __half2*)&p3;
#pragma unroll
        for (int i = 0; i < 4; i++) {
            float2 f0 = __half22float2(h0[i]);
            float2 f1 = __half22float2(h1[i]);
            float2 f2 = __half22float2(h2[i]);
            float2 f3 = __half22float2(h3[i]);
            av[2 * i + 0] += w0 * f0.x + w1 * f1.x + w2 * f2.x + w3 * f3.x;
            av[2 * i + 1] += w0 * f0.y + w1 * f1.y + w2 * f2.y + w3 * f3.y;
        }
    }
    for (; kk < cap; kk++) {
        int j0 = sj[wslot][kk];
        float4 e0v = se[wslot][kk];
        float w0 = s16 ? (s8 ? e0v.w * i3 : e0v.z * i2) : (s8 ? e0v.y * i1 : e0v.x * i0);
        float4 p0 = *(const float4*)(g_h1h + (size_t)j0 * F1 + col);
        const __half2* h0 = (const __half2*)&p0;
#pragma unroll
        for (int i = 0; i < 4; i++) {
            float2 f0 = __half22float2(h0[i]);
            av[2 * i + 0] += w0 * f0.x;
            av[2 * i + 1] += w0 * f0.y;
        }
    }
    for (; kk < deg; kk++) {      // rare fallback: degree > CAP
        int j0 = g_srcidx[beg + kk];
        float4 as = *(const float4*)(g_as1 + j0 * 4);
        float e0 = __expf(lrelu(as.x + ad.x));
        float e1 = __expf(lrelu(as.y + ad.y));
        float e2 = __expf(lrelu(as.z + ad.z));
        float e3 = __expf(lrelu(as.w + ad.w));
        float w0 = s16 ? (s8 ? e3 * i3 : e2 * i2) : (s8 ? e1 * i1 : e0 * i0);
        float4 p0 = *(const float4*)(g_h1h + (size_t)j0 * F1 + col);
        const __half2* h0 = (const __half2*)&p0;
#pragma unroll
        for (int i = 0; i < 4; i++) {
            float2 f0 = __half22float2(h0[i]);
            av[2 * i + 0] += w0 * f0.x;
            av[2 * i + 1] += w0 * f0.y;
        }
    }

    float4 bA = *(const float4*)(b1 + col);
    float4 bB = *(const float4*)(b1 + col + 4);
    __half2 pack[4];
    pack[0] = __floats2half2_rn(fmaxf(av[0] + bA.x, 0.f), fmaxf(av[1] + bA.y, 0.f));
    pack[1] = __floats2half2_rn(fmaxf(av[2] + bA.z, 0.f), fmaxf(av[3] + bA.w, 0.f));
    pack[2] = __floats2half2_rn(fmaxf(av[4] + bB.x, 0.f), fmaxf(av[5] + bB.y, 0.f));
    pack[3] = __floats2half2_rn(fmaxf(av[6] + bB.z, 0.f), fmaxf(av[7] + bB.w, 0.f));
    *(float4*)(g_out1h + (size_t)node * F1 + col) = *(const float4*)pack;
}

// ---------------- conv2: fused softmax+aggregation (warp/node, smem-staged) --
__global__ __launch_bounds__(256) void agg2_k(const float* __restrict__ b2) {
    __shared__ int   sj[8][CAP];
    __shared__ float sw[8][CAP];
    int wslot = threadIdx.x >> 5, lane = threadIdx.x & 31;
    int node = blockIdx.x * 8 + wslot;
    if (node >= NN) return;
    int beg = g_off[node], deg = g_off[node + 1] - beg;

    float ad = g_ad2[node];
    float den = 0.f;
    for (int kk = lane; kk < deg; kk += 32) {
        int j = g_srcidx[beg + kk];
        float e = __expf(lrelu(g_as2[j] + ad));
        den += e;
        if (kk < CAP) { sj[wslot][kk] = j; sw[wslot][kk] = e; }
    }
#pragma unroll
    for (int o = 16; o; o >>= 1) den += __shfl_xor_sync(0xffffffffu, den, o);
    float inv = 1.f / (den + 1e-16f);
    __syncwarp();

    float a0 = 0.f, a1 = 0.f;
    int c = lane * 2;
    int cap = deg < CAP ? deg : CAP;
    int kk = 0;
    for (; kk + 4 <= cap; kk += 4) {
        int j0 = sj[wslot][kk],     j1 = sj[wslot][kk + 1];
        int j2 = sj[wslot][kk + 2], j3 = sj[wslot][kk + 3];
        float w0 = sw[wslot][kk] * inv,     w1 = sw[wslot][kk + 1] * inv;
        float w2 = sw[wslot][kk + 2] * inv, w3 = sw[wslot][kk + 3] * inv;
        float2 v0 = __half22float2(*(const __half2*)(g_h2h + (size_t)j0 * OUTC + c));
        float2 v1 = __half22float2(*(const __half2*)(g_h2h + (size_t)j1 * OUTC + c));
        float2 v2 = __half22float2(*(const __half2*)(g_h2h + (size_t)j2 * OUTC + c));
        float2 v3 = __half22float2(*(const __half2*)(g_h2h + (size_t)j3 * OUTC + c));
        a0 += w0 * v0.x + w1 * v1.x + w2 * v2.x + w3 * v3.x;
        a1 += w0 * v0.y + w1 * v1.y + w2 * v2.y + w3 * v3.y;
    }
    for (; kk < cap; kk++) {
        int j0 = sj[wslot][kk];
        float w0 = sw[wslot][kk] * inv;
        float2 v0 = __half22float2(*(const __half2*)(g_h2h + (size_t)j0 * OUTC + c));
        a0 += w0 * v0.x; a1 += w0 * v0.y;
    }
    for (; kk < deg; kk++) {      // rare fallback
        int j0 = g_srcidx[beg + kk];
        float w0 = __expf(lrelu(g_as2[j0] + ad)) * inv;
        float2 v0 = __half22float2(*(const __half2*)(g_h2h + (size_t)j0 * OUTC + c));
        a0 += w0 * v0.x; a1 += w0 * v0.y;
    }
    float2 bb = *(const float2*)(b2 + c);
    *(__half2*)(g_out2h + (size_t)node * OUTC + c) = __floats2half2_rn(a0 + bb.x, a1 + bb.y);
}

// ---------------- decode: logits (8 lanes per edge, 4 edges per warp) --------
__global__ void decode_k(const int* __restrict__ pos, const int* __restrict__ neg,
                         float* __restrict__ out) {
    int g = blockIdx.x * blockDim.x + threadIdx.x;
    int e = g >> 3, lane = g & 7;
    if (e >= 2 * EE) return;
    int a, b;
    if (e < EE) { a = pos[e]; b = pos[EE + e]; }
    else        { int t = e - EE; a = neg[t]; b = neg[EE + t]; }
    int c = lane * 8;
    float4 pa = *(const float4*)(g_out2h + (size_t)a * OUTC + c);
    float4 pb = *(const float4*)(g_out2h + (size_t)b * OUTC + c);
    const __half2* ha = (const __half2*)&pa;
    const __half2* hb = (const __half2*)&pb;
    float acc = 0.f;
#pragma unroll
    for (int i = 0; i < 4; i++) {
        float2 fa = __half22float2(ha[i]);
        float2 fb = __half22float2(hb[i]);
        acc += fa.x * fb.x + fa.y * fb.y;
    }
#pragma unroll
    for (int o = 4; o; o >>= 1) acc += __shfl_xor_sync(0xffffffffu, acc, o);
    if (!lane) out[e] = acc;
}

// ---------------- launch ----------------
extern "C" void kernel_launch(void* const* d_in, const int* in_sizes, int n_in,
                              void* d_out, int out_size) {
    const float* x    = (const float*)d_in[0];
    const int*   pos  = (const int*)d_in[1];
    const int*   neg  = (const int*)d_in[2];
    const float* W1   = (const float*)d_in[3];
    const float* as1v = (const float*)d_in[4];
    const float* ad1v = (const float*)d_in[5];
    const float* b1   = (const float*)d_in[6];
    const float* W2   = (const float*)d_in[7];
    const float* as2v = (const float*)d_in[8];
    const float* ad2v = (const float*)d_in[9];
    const float* b2   = (const float*)d_in[10];
    float* out = (float*)d_out;
    (void)in_sizes; (void)n_in; (void)out_size;

    static cudaStream_t s1 = nullptr;
    static cudaEvent_t evFork = nullptr, evJoin = nullptr;
    if (s1 == nullptr) {
        cudaStreamCreateWithFlags(&s1, cudaStreamNonBlocking);
        cudaEventCreateWithFlags(&evFork, cudaEventDisableTiming);
        cudaEventCreateWithFlags(&evJoin, cudaEventDisableTiming);
    }

    // fork: CSR build on s1, concurrent with gemm1 on the main stream
    cudaEventRecord(evFork, 0);
    cudaStreamWaitEvent(s1, evFork, 0);
    init_off_k<<<(NN + 256) / 256, 256, 0, s1>>>();
    hist_k<<<(EE + 255) / 256, 256, 0, s1>>>(pos);
    scan_k<<<1, 1024, 0, s1>>>();
    scatter_k<<<(ET + 255) / 256, 256, 0, s1>>>(pos);
    cudaEventRecord(evJoin, s1);

    // conv1 linear + fused attention dots
    mma_gemm_k<0><<<dim3(F1 / 64, (NN + 127) / 128), 256>>>(x, W1, as1v, ad1v, NN, F1, INC);

    cudaStreamWaitEvent(0, evJoin, 0);
    agg1_k<<<(NN + 7) / 8, 256>>>(b1);

    // conv2
    mma_gemm_k<1><<<dim3(OUTC / 64, (NN + 127) / 128), 256>>>(nullptr, W2, as2v, ad2v, NN, OUTC, F1);
    agg2_k<<<(NN + 7) / 8, 256>>>(b2);

    // decode
    decode_k<<<(2 * EE * 8 + 255) / 256, 256>>>(pos, neg, out);
}

// round 11
// speedup vs baseline: 2.5965x; 1.1674x over previous
#include <cuda_runtime.h>
#include <cuda_fp16.h>
#include <math.h>
#include <stdint.h>

#define NN    50000
#define EE    800000
#define INC   128
#define HIDC  64
#define NH    4
#define OUTC  64
#define F1    (NH * HIDC)        // 256
#define ET    (EE + NN)          // edges + self loops = 850000

// ---------------- scratch (device globals; no allocation) ----------------
__device__ __half g_h1h  [(size_t)NN * F1];   // x @ W1   (fp16 storage)
__device__ __half g_out1h[(size_t)NN * F1];   // z        (fp16 storage)
__device__ float  g_as1 [NN * NH];
__device__ float  g_ad1 [NN * NH];
__device__ __half g_h2h [(size_t)NN * OUTC];  // z @ W2   (fp16 storage)
__device__ __half g_out2h[(size_t)NN * OUTC]; // z2       (fp16 storage)
__device__ float  g_as2 [NN];
__device__ float  g_ad2 [NN];
// CSR by destination (shared by both conv layers)
__device__ int    g_off [NN + 1];
__device__ int    g_fill[NN];
__device__ int    g_srcidx[ET];

__device__ __forceinline__ float lrelu(float v) { return v > 0.f ? v : 0.2f * v; }

// ---------------- CSR build ----------------
__global__ void init_off_k() {
    int i = blockIdx.x * blockDim.x + threadIdx.x;
    if (i <= NN) g_off[i] = (i == 0) ? 0 : 1;   // each node has 1 self loop
}

__global__ void hist_k(const int* __restrict__ ei) {
    int e = blockIdx.x * blockDim.x + threadIdx.x;
    if (e >= EE) return;
    atomicAdd(&g_off[ei[EE + e] + 1], 1);
}

// single-block 3-phase inclusive scan over g_off[0..NN]
__global__ void scan_k() {
    const int L = NN + 1;
    const int CH = (L + 1023) / 1024;
    __shared__ int wsum[32];
    int t = threadIdx.x, lane = t & 31, wid = t >> 5;
    int beg = t * CH;
    int end = beg + CH; if (end > L) end = L;

    int s = 0;
    for (int i = beg; i < end; i++) s += g_off[i];

    int incl = s;
#pragma unroll
    for (int o = 1; o < 32; o <<= 1) {
        int v = __shfl_up_sync(0xffffffffu, incl, o);
        if (lane >= o) incl += v;
    }
    if (lane == 31) wsum[wid] = incl;
    __syncthreads();
    if (wid == 0) {
        int w = wsum[lane];
        int wi = w;
#pragma unroll
        for (int o = 1; o < 32; o <<= 1) {
            int v = __shfl_up_sync(0xffffffffu, wi, o);
            if (lane >= o) wi += v;
        }
        wsum[lane] = wi - w;
    }
    __syncthreads();

    int run = (incl - s) + wsum[wid];
    for (int i = beg; i < end; i++) {
        run += g_off[i];
        g_off[i] = run;
        if (i < NN) g_fill[i] = run;
    }
}

__global__ void scatter_k(const int* __restrict__ ei) {
    int e = blockIdx.x * blockDim.x + threadIdx.x;
    if (e >= ET) return;
    int s, d;
    if (e < EE) { s = ei[e]; d = ei[EE + e]; } else { s = d = e - EE; }
    int p = atomicAdd(&g_fill[d], 1);
    g_srcidx[p] = s;
}

// ---------------- fp16 tensor-core GEMM + fused attention --------------------
// C[M,N] = A[M,K] @ B[K,N]; BM=128, BN=64, BK=16; 8 warps, each 32x32.
// A staged [row][k] halves (stride 18), B staged [n][k] halves (stride 18).
#define AS_STRIDE 18

__device__ __forceinline__ void mma_f16(float* d, uint32_t a0, uint32_t a1,
                                        uint32_t a2, uint32_t a3,
                                        uint32_t b0, uint32_t b1) {
    asm volatile(
        "mma.sync.aligned.m16n8k16.row.col.f32.f16.f16.f32 "
        "{%0,%1,%2,%3}, {%4,%5,%6,%7}, {%8,%9}, {%0,%1,%2,%3};\n"
        : "+f"(d[0]), "+f"(d[1]), "+f"(d[2]), "+f"(d[3])
        : "r"(a0), "r"(a1), "r"(a2), "r"(a3), "r"(b0), "r"(b1));
}

// MODE 0: A = x (fp32 ext), C = g_h1h,  attn -> g_as1/g_ad1 per head (blockIdx.x)
// MODE 1: A = g_out1h (fp16), C = g_h2h, attn -> g_as2/g_ad2   [PDL secondary]
template <int MODE>
__global__ __launch_bounds__(256) void mma_gemm_k(const float* __restrict__ Aext,
                                                  const float* __restrict__ B,
                                                  const float* __restrict__ att_s,
                                                  const float* __restrict__ att_d,
                                                  int M, int N, int K) {
    __shared__ __align__(16) __half As[128 * AS_STRIDE];
    __shared__ __align__(16) __half Bs[64 * AS_STRIDE];
    __shared__ float sAs[128], sAd[128];

    int tid = threadIdx.x;
    int wid = tid >> 5, lane = tid & 31;
    int warp_m = wid >> 1, warp_n = wid & 1;
    int m_warp = warp_m * 32, n_warp = warp_n * 32;
    int g = lane >> 2, c = lane & 3;
    int rowBase = blockIdx.y * 128, colBase = blockIdx.x * 64;

    if (MODE == 1) cudaGridDependencySynchronize();   // wait for agg1's z

    if (tid < 128) { sAs[tid] = 0.f; sAd[tid] = 0.f; }

    float acc[2][4][4] = {};

    for (int k0 = 0; k0 < K; k0 += 16) {
        // ---- stage A: 128 rows x 16 k (halves) ----
        {
            int row = tid >> 1, kq = (tid & 1) * 8;
            int gm = rowBase + row;
            __half2 hv[4];
            if (MODE == 0) {
                float4 v0 = make_float4(0.f, 0.f, 0.f, 0.f), v1 = v0;
                if (gm < M) {
                    const float* ap = Aext + (size_t)gm * K + k0 + kq;
                    v0 = *(const float4*)ap;
                    v1 = *(const float4*)(ap + 4);
                }
                hv[0] = __floats2half2_rn(v0.x, v0.y);
                hv[1] = __floats2half2_rn(v0.z, v0.w);
                hv[2] = __floats2half2_rn(v1.x, v1.y);
                hv[3] = __floats2half2_rn(v1.z, v1.w);
            } else {
                if (gm < M) {
                    float4 p = *(const float4*)(g_out1h + (size_t)gm * K + k0 + kq);
                    const __half2* hp = (const __half2*)&p;
                    hv[0] = hp[0]; hv[1] = hp[1]; hv[2] = hp[2]; hv[3] = hp[3];
                } else {
                    hv[0] = hv[1] = hv[2] = hv[3] = __floats2half2_rn(0.f, 0.f);
                }
            }
            __half2* dst = (__half2*)&As[row * AS_STRIDE + kq];
            dst[0] = hv[0]; dst[1] = hv[1]; dst[2] = hv[2]; dst[3] = hv[3];
        }
        // ---- stage B transposed: Bs[n][k], 16 k x 64 n ----
        {
            int kr = tid >> 4, nq = (tid & 15) * 4;
            float4 v = *(const float4*)(B + (size_t)(k0 + kr) * N + colBase + nq);
            Bs[(nq + 0) * AS_STRIDE + kr] = __float2half_rn(v.x);
            Bs[(nq + 1) * AS_STRIDE + kr] = __float2half_rn(v.y);
            Bs[(nq + 2) * AS_STRIDE + kr] = __float2half_rn(v.z);
            Bs[(nq + 3) * AS_STRIDE + kr] = __float2half_rn(v.w);
        }
        __syncthreads();

        uint32_t a[2][4], b[4][2];
#pragma unroll
        for (int t = 0; t < 2; t++) {
            int r0 = (m_warp + t * 16 + g) * AS_STRIDE + 2 * c;
            int r1 = r0 + 8 * AS_STRIDE;
            a[t][0] = *(const uint32_t*)&As[r0];
            a[t][1] = *(const uint32_t*)&As[r1];
            a[t][2] = *(const uint32_t*)&As[r0 + 8];
            a[t][3] = *(const uint32_t*)&As[r1 + 8];
        }
#pragma unroll
        for (int j = 0; j < 4; j++) {
            int nb = (n_warp + j * 8 + g) * AS_STRIDE + 2 * c;
            b[j][0] = *(const uint32_t*)&Bs[nb];
            b[j][1] = *(const uint32_t*)&Bs[nb + 8];
        }
#pragma unroll
        for (int t = 0; t < 2; t++)
#pragma unroll
            for (int j = 0; j < 4; j++)
                mma_f16(acc[t][j], a[t][0], a[t][1], a[t][2], a[t][3], b[j][0], b[j][1]);
        __syncthreads();
    }

    // write C as fp16
    __half* Ch = (MODE == 0) ? g_h1h : g_h2h;
#pragma unroll
    for (int t = 0; t < 2; t++)
#pragma unroll
        for (int j = 0; j < 4; j++) {
            int r0 = rowBase + m_warp + t * 16 + g;
            int r1 = r0 + 8;
            int cc = colBase + n_warp + j * 8 + 2 * c;
            if (r0 < M)
                *(__half2*)&Ch[(size_t)r0 * N + cc] = __floats2half2_rn(acc[t][j][0], acc[t][j][1]);
            if (r1 < M)
                *(__half2*)&Ch[(size_t)r1 * N + cc] = __floats2half2_rn(acc[t][j][2], acc[t][j][3]);
        }

    // fused attention dots over this block's 64 columns
#pragma unroll
    for (int t = 0; t < 2; t++) {
        float s0 = 0.f, d0 = 0.f, s1 = 0.f, d1 = 0.f;
#pragma unroll
        for (int j = 0; j < 4; j++) {
            int cg = colBase + n_warp + j * 8 + 2 * c;
            float w0 = __ldg(att_s + cg), w1 = __ldg(att_s + cg + 1);
            float v0 = __ldg(att_d + cg), v1 = __ldg(att_d + cg + 1);
            s0 += acc[t][j][0] * w0 + acc[t][j][1] * w1;
            d0 += acc[t][j][0] * v0 + acc[t][j][1] * v1;
            s1 += acc[t][j][2] * w0 + acc[t][j][3] * w1;
            d1 += acc[t][j][2] * v0 + acc[t][j][3] * v1;
        }
#pragma unroll
        for (int o = 1; o < 4; o <<= 1) {
            s0 += __shfl_xor_sync(0xffffffffu, s0, o);
            d0 += __shfl_xor_sync(0xffffffffu, d0, o);
            s1 += __shfl_xor_sync(0xffffffffu, s1, o);
            d1 += __shfl_xor_sync(0xffffffffu, d1, o);
        }
        if (c == 0) {
            int rl = m_warp + t * 16 + g;
            atomicAdd(&sAs[rl], s0);     atomicAdd(&sAd[rl], d0);
            atomicAdd(&sAs[rl + 8], s1); atomicAdd(&sAd[rl + 8], d1);
        }
    }
    __syncthreads();
    if (tid < 128) {
        int gm = rowBase + tid;
        if (gm < M) {
            if (MODE == 0) {
                g_as1[gm * NH + blockIdx.x] = sAs[tid];
                g_ad1[gm * NH + blockIdx.x] = sAd[tid];
            } else {
                g_as2[gm] = sAs[tid];
                g_ad2[gm] = sAd[tid];
            }
        }
    }
}

// ---------------- conv1: fused softmax+aggregation (warp/node, smem-staged) --
#define CAP 64
__global__ __launch_bounds__(256) void agg1_k(const float* __restrict__ b1) {
    __shared__ int    sj[8][CAP];
    __shared__ float4 se[8][CAP];
    int wslot = threadIdx.x >> 5, lane = threadIdx.x & 31;
    int node = blockIdx.x * 8 + wslot;
    if (node >= NN) return;
    int beg = g_off[node], deg = g_off[node + 1] - beg;   // CSR: event-ordered, safe

    cudaGridDependencySynchronize();                       // wait for gemm1 outputs

    float4 ad = *(const float4*)(g_ad1 + node * 4);
    float d0 = 0.f, d1 = 0.f, d2 = 0.f, d3 = 0.f;
    for (int kk = lane; kk < deg; kk += 32) {
        int j = g_srcidx[beg + kk];
        float4 as = *(const float4*)(g_as1 + j * 4);
        float e0 = __expf(lrelu(as.x + ad.x));
        float e1 = __expf(lrelu(as.y + ad.y));
        float e2 = __expf(lrelu(as.z + ad.z));
        float e3 = __expf(lrelu(as.w + ad.w));
        d0 += e0; d1 += e1; d2 += e2; d3 += e3;
        if (kk < CAP) { sj[wslot][kk] = j; se[wslot][kk] = make_float4(e0, e1, e2, e3); }
    }
#pragma unroll
    for (int o = 16; o; o >>= 1) {
        d0 += __shfl_xor_sync(0xffffffffu, d0, o);
        d1 += __shfl_xor_sync(0xffffffffu, d1, o);
        d2 += __shfl_xor_sync(0xffffffffu, d2, o);
        d3 += __shfl_xor_sync(0xffffffffu, d3, o);
    }
    float i0 = 1.f / (d0 + 1e-16f), i1 = 1.f / (d1 + 1e-16f);
    float i2 = 1.f / (d2 + 1e-16f), i3 = 1.f / (d3 + 1e-16f);
    __syncwarp();

    const bool s8 = (lane & 8) != 0, s16 = (lane & 16) != 0;
    float av[8] = {};
    int col = lane * 8;
    int cap = deg < CAP ? deg : CAP;

    int kk = 0;
    for (; kk + 4 <= cap; kk += 4) {
        int j0 = sj[wslot][kk],     j1 = sj[wslot][kk + 1];
        int j2 = sj[wslot][kk + 2], j3 = sj[wslot][kk + 3];
        float4 e0v = se[wslot][kk],     e1v = se[wslot][kk + 1];
        float4 e2v = se[wslot][kk + 2], e3v = se[wslot][kk + 3];
        float w0 = s16 ? (s8 ? e0v.w * i3 : e0v.z * i2) : (s8 ? e0v.y * i1 : e0v.x * i0);
        float w1 = s16 ? (s8 ? e1v.w * i3 : e1v.z * i2) : (s8 ? e1v.y * i1 : e1v.x * i0);
        float w2 = s16 ? (s8 ? e2v.w * i3 : e2v.z * i2) : (s8 ? e2v.y * i1 : e2v.x * i0);
        float w3 = s16 ? (s8 ? e3v.w * i3 : e3v.z * i2) : (s8 ? e3v.y * i1 : e3v.x * i0);
        float4 p0 = *(const float4*)(g_h1h + (size_t)j0 * F1 + col);
        float4 p1 = *(const float4*)(g_h1h + (size_t)j1 * F1 + col);
        float4 p2 = *(const float4*)(g_h1h + (size_t)j2 * F1 + col);
        float4 p3 = *(const float4*)(g_h1h + (size_t)j3 * F1 + col);
        const __half2* h0 = (const __half2*)&p0;
        const __half2* h1 = (const __half2*)&p1;
        const __half2* h2 = (const __half2*)&p2;
        const __half2* h3 = (const __half2*)&p3;
#pragma unroll
        for (int i = 0; i < 4; i++) {
            float2 f0 = __half22float2(h0[i]);
            float2 f1 = __half22float2(h1[i]);
            float2 f2 = __half22float2(h2[i]);
            float2 f3 = __half22float2(h3[i]);
            av[2 * i + 0] += w0 * f0.x + w1 * f1.x + w2 * f2.x + w3 * f3.x;
            av[2 * i + 1] += w0 * f0.y + w1 * f1.y + w2 * f2.y + w3 * f3.y;
        }
    }
    for (; kk < cap; kk++) {
        int j0 = sj[wslot][kk];
        float4 e0v = se[wslot][kk];
        float w0 = s16 ? (s8 ? e0v.w * i3 : e0v.z * i2) : (s8 ? e0v.y * i1 : e0v.x * i0);
        float4 p0 = *(const float4*)(g_h1h + (size_t)j0 * F1 + col);
        const __half2* h0 = (const __half2*)&p0;
#pragma unroll
        for (int i = 0; i < 4; i++) {
            float2 f0 = __half22float2(h0[i]);
            av[2 * i + 0] += w0 * f0.x;
            av[2 * i + 1] += w0 * f0.y;
        }
    }
    for (; kk < deg; kk++) {      // rare fallback: degree > CAP
        int j0 = g_srcidx[beg + kk];
        float4 as = *(const float4*)(g_as1 + j0 * 4);
        float e0 = __expf(lrelu(as.x + ad.x));
        float e1 = __expf(lrelu(as.y + ad.y));
        float e2 = __expf(lrelu(as.z + ad.z));
        float e3 = __expf(lrelu(as.w + ad.w));
        float w0 = s16 ? (s8 ? e3 * i3 : e2 * i2) : (s8 ? e1 * i1 : e0 * i0);
        float4 p0 = *(const float4*)(g_h1h + (size_t)j0 * F1 + col);
        const __half2* h0 = (const __half2*)&p0;
#pragma unroll
        for (int i = 0; i < 4; i++) {
            float2 f0 = __half22float2(h0[i]);
            av[2 * i + 0] += w0 * f0.x;
            av[2 * i + 1] += w0 * f0.y;
        }
    }

    float4 bA = *(const float4*)(b1 + col);
    float4 bB = *(const float4*)(b1 + col + 4);
    __half2 pack[4];
    pack[0] = __floats2half2_rn(fmaxf(av[0] + bA.x, 0.f), fmaxf(av[1] + bA.y, 0.f));
    pack[1] = __floats2half2_rn(fmaxf(av[2] + bA.z, 0.f), fmaxf(av[3] + bA.w, 0.f));
    pack[2] = __floats2half2_rn(fmaxf(av[4] + bB.x, 0.f), fmaxf(av[5] + bB.y, 0.f));
    pack[3] = __floats2half2_rn(fmaxf(av[6] + bB.z, 0.f), fmaxf(av[7] + bB.w, 0.f));
    *(float4*)(g_out1h + (size_t)node * F1 + col) = *(const float4*)pack;
}

// ---------------- conv2: fused softmax+aggregation (warp/node, smem-staged) --
__global__ __launch_bounds__(256) void agg2_k(const float* __restrict__ b2) {
    __shared__ int   sj[8][CAP];
    __shared__ float sw[8][CAP];
    int wslot = threadIdx.x >> 5, lane = threadIdx.x & 31;
    int node = blockIdx.x * 8 + wslot;
    if (node >= NN) return;
    int beg = g_off[node], deg = g_off[node + 1] - beg;   // CSR safe

    cudaGridDependencySynchronize();                       // wait for gemm2 outputs

    float ad = g_ad2[node];
    float den = 0.f;
    for (int kk = lane; kk < deg; kk += 32) {
        int j = g_srcidx[beg + kk];
        float e = __expf(lrelu(g_as2[j] + ad));
        den += e;
        if (kk < CAP) { sj[wslot][kk] = j; sw[wslot][kk] = e; }
    }
#pragma unroll
    for (int o = 16; o; o >>= 1) den += __shfl_xor_sync(0xffffffffu, den, o);
    float inv = 1.f / (den + 1e-16f);
    __syncwarp();

    float a0 = 0.f, a1 = 0.f;
    int c = lane * 2;
    int cap = deg < CAP ? deg : CAP;
    int kk = 0;
    for (; kk + 4 <= cap; kk += 4) {
        int j0 = sj[wslot][kk],     j1 = sj[wslot][kk + 1];
        int j2 = sj[wslot][kk + 2], j3 = sj[wslot][kk + 3];
        float w0 = sw[wslot][kk] * inv,     w1 = sw[wslot][kk + 1] * inv;
        float w2 = sw[wslot][kk + 2] * inv, w3 = sw[wslot][kk + 3] * inv;
        float2 v0 = __half22float2(*(const __half2*)(g_h2h + (size_t)j0 * OUTC + c));
        float2 v1 = __half22float2(*(const __half2*)(g_h2h + (size_t)j1 * OUTC + c));
        float2 v2 = __half22float2(*(const __half2*)(g_h2h + (size_t)j2 * OUTC + c));
        float2 v3 = __half22float2(*(const __half2*)(g_h2h + (size_t)j3 * OUTC + c));
        a0 += w0 * v0.x + w1 * v1.x + w2 * v2.x + w3 * v3.x;
        a1 += w0 * v0.y + w1 * v1.y + w2 * v2.y + w3 * v3.y;
    }
    for (; kk < cap; kk++) {
        int j0 = sj[wslot][kk];
        float w0 = sw[wslot][kk] * inv;
        float2 v0 = __half22float2(*(const __half2*)(g_h2h + (size_t)j0 * OUTC + c));
        a0 += w0 * v0.x; a1 += w0 * v0.y;
    }
    for (; kk < deg; kk++) {      // rare fallback
        int j0 = g_srcidx[beg + kk];
        float w0 = __expf(lrelu(g_as2[j0] + ad)) * inv;
        float2 v0 = __half22float2(*(const __half2*)(g_h2h + (size_t)j0 * OUTC + c));
        a0 += w0 * v0.x; a1 += w0 * v0.y;
    }
    float2 bb = *(const float2*)(b2 + c);
    *(__half2*)(g_out2h + (size_t)node * OUTC + c) = __floats2half2_rn(a0 + bb.x, a1 + bb.y);
}

// ---------------- decode: logits (8 lanes per edge, 4 edges per warp) --------
__global__ void decode_k(const int* __restrict__ pos, const int* __restrict__ neg,
                         float* __restrict__ out) {
    int g = blockIdx.x * blockDim.x + threadIdx.x;
    int e = g >> 3, lane = g & 7;
    if (e >= 2 * EE) return;
    int a, b;
    if (e < EE) { a = pos[e]; b = pos[EE + e]; }
    else        { int t = e - EE; a = neg[t]; b = neg[EE + t]; }

    cudaGridDependencySynchronize();      // index loads above overlap agg2 tail

    int c = lane * 8;
    float4 pa = *(const float4*)(g_out2h + (size_t)a * OUTC + c);
    float4 pb = *(const float4*)(g_out2h + (size_t)b * OUTC + c);
    const __half2* ha = (const __half2*)&pa;
    const __half2* hb = (const __half2*)&pb;
    float acc = 0.f;
#pragma unroll
    for (int i = 0; i < 4; i++) {
        float2 fa = __half22float2(ha[i]);
        float2 fb = __half22float2(hb[i]);
        acc += fa.x * fb.x + fa.y * fb.y;
    }
#pragma unroll
    for (int o = 4; o; o >>= 1) acc += __shfl_xor_sync(0xffffffffu, acc, o);
    if (!lane) out[e] = acc;
}

// ---------------- launch ----------------
extern "C" void kernel_launch(void* const* d_in, const int* in_sizes, int n_in,
                              void* d_out, int out_size) {
    const float* x    = (const float*)d_in[0];
    const int*   pos  = (const int*)d_in[1];
    const int*   neg  = (const int*)d_in[2];
    const float* W1   = (const float*)d_in[3];
    const float* as1v = (const float*)d_in[4];
    const float* ad1v = (const float*)d_in[5];
    const float* b1   = (const float*)d_in[6];
    const float* W2   = (const float*)d_in[7];
    const float* as2v = (const float*)d_in[8];
    const float* ad2v = (const float*)d_in[9];
    const float* b2   = (const float*)d_in[10];
    float* out = (float*)d_out;
    (void)in_sizes; (void)n_in; (void)out_size;

    static cudaStream_t s1 = nullptr;
    static cudaEvent_t evFork = nullptr, evJoin = nullptr;
    if (s1 == nullptr) {
        cudaStreamCreateWithFlags(&s1, cudaStreamNonBlocking);
        cudaEventCreateWithFlags(&evFork, cudaEventDisableTiming);
        cudaEventCreateWithFlags(&evJoin, cudaEventDisableTiming);
    }

    // PDL launch config (opportunistic overlap with preceding kernel)
    cudaLaunchAttribute pdlAttr[1];
    pdlAttr[0].id = cudaLaunchAttributeProgrammaticStreamSerialization;
    pdlAttr[0].val.programmaticStreamSerializationAllowed = 1;

    // fork: CSR build on s1, concurrent with gemm1 on the main stream
    cudaEventRecord(evFork, 0);
    cudaStreamWaitEvent(s1, evFork, 0);
    init_off_k<<<(NN + 256) / 256, 256, 0, s1>>>();
    hist_k<<<(EE + 255) / 256, 256, 0, s1>>>(pos);
    scan_k<<<1, 1024, 0, s1>>>();
    scatter_k<<<(ET + 255) / 256, 256, 0, s1>>>(pos);
    cudaEventRecord(evJoin, s1);

    // conv1 linear + fused attention dots (normal launch)
    mma_gemm_k<0><<<dim3(F1 / 64, (NN + 127) / 128), 256>>>(x, W1, as1v, ad1v, NN, F1, INC);

    cudaStreamWaitEvent(0, evJoin, 0);

    // agg1 (PDL secondary of gemm1)
    {
        cudaLaunchConfig_t cfg = {};
        cfg.gridDim = dim3((NN + 7) / 8); cfg.blockDim = dim3(256);
        cfg.stream = 0; cfg.attrs = pdlAttr; cfg.numAttrs = 1;
        cudaLaunchKernelEx(&cfg, agg1_k, b1);
    }
    // gemm2 (PDL secondary of agg1)
    {
        cudaLaunchConfig_t cfg = {};
        cfg.gridDim = dim3(OUTC / 64, (NN + 127) / 128); cfg.blockDim = dim3(256);
        cfg.stream = 0; cfg.attrs = pdlAttr; cfg.numAttrs = 1;
        cudaLaunchKernelEx(&cfg, mma_gemm_k<1>, (const float*)nullptr, W2, as2v, ad2v,
                           (int)NN, (int)OUTC, (int)F1);
    }
    // agg2 (PDL secondary of gemm2)
    {
        cudaLaunchConfig_t cfg = {};
        cfg.gridDim = dim3((NN + 7) / 8); cfg.blockDim = dim3(256);
        cfg.stream = 0; cfg.attrs = pdlAttr; cfg.numAttrs = 1;
        cudaLaunchKernelEx(&cfg, agg2_k, b2);
    }
    // decode (PDL secondary of agg2)
    {
        cudaLaunchConfig_t cfg = {};
        cfg.gridDim = dim3((2 * EE * 8 + 255) / 256); cfg.blockDim = dim3(256);
        cfg.stream = 0; cfg.attrs = pdlAttr; cfg.numAttrs = 1;
        cudaLaunchKernelEx(&cfg, decode_k, pos, neg, out);
    }
}